// round 2
// baseline (speedup 1.0000x reference)
#include <cuda_runtime.h>

// Problem constants
#define NN 1024
#define TT 64
#define BB 16
#define CC 32
// batch of the main GEMM = B*C_OUT = 512

// ---------------------------------------------------------------------------
// Scratch (device globals; no allocations allowed)
// ---------------------------------------------------------------------------
__device__ __align__(128) float g_U [BB * CC * 2 * NN * TT]; // [b][o][2N][T]  (u1 rows 0..N-1, u2 rows N..2N-1)  256MB
__device__ __align__(128) float g_U0[BB * CC * NN * TT];     // [b][o][N][T]  128MB
__device__ __align__(128) float g_M [NN * 2 * NN];           // [n][m] cols 0..N-1 = M1, N..2N-1 = M2   8MB
__device__ __align__(128) float g_G1[NN * NN];               // 4MB scratch
__device__ __align__(128) float g_G2[NN * NN];               // 4MB scratch
__device__ __align__(128) float g_S [NN * NN];               // 4MB scratch

// ---------------------------------------------------------------------------
// Generic fp32 GEMM:  C[bz] = A @ B[bz] (+ Cadd[bz]) (+ bias[bz%32])
// Row-major. Tile: BM=128, BN=64, BK=16. 256 threads, 8x4 microtile/thread.
// Requirements: M % 128 == 0, Ncols % 64 == 0, K % 16 == 0, lda/ldb/ldc % 4 == 0.
// ---------------------------------------------------------------------------
__global__ __launch_bounds__(256) void gemm_f32_128x64(
    const float* __restrict__ A, const float* __restrict__ B, float* __restrict__ C,
    int K, int lda, int ldb, int ldc,
    long long strideB, long long strideC,
    const float* __restrict__ Cadd, const float* __restrict__ bias)
{
    const int tid  = threadIdx.x;
    const int tx   = tid & 15;   // col group: cols tx*4 .. tx*4+3
    const int ty   = tid >> 4;   // row group: rows ty*8 .. ty*8+7
    const int row0 = blockIdx.y * 128;
    const int col0 = blockIdx.x * 64;
    const long long bz = blockIdx.z;

    const float* Bp = B + bz * strideB;

    __shared__ float As[16 * 129];   // [kk][r], stride 129 => conflict-free transpose stores
    __shared__ float Bs[16 * 64];    // [kk][c]

    float acc[8][4];
#pragma unroll
    for (int i = 0; i < 8; i++)
#pragma unroll
        for (int j = 0; j < 4; j++) acc[i][j] = 0.0f;

    for (int k0 = 0; k0 < K; k0 += 16) {
        // --- load A tile (128 x 16), transposed into As ---
#pragma unroll
        for (int i = 0; i < 2; i++) {
            int vidx = tid + i * 256;          // 0..511 float4's
            int r    = vidx >> 2;              // 0..127
            int kk4  = (vidx & 3) << 2;        // 0,4,8,12
            const float4 v = *reinterpret_cast<const float4*>(
                A + (long long)(row0 + r) * lda + k0 + kk4);
            As[(kk4 + 0) * 129 + r] = v.x;
            As[(kk4 + 1) * 129 + r] = v.y;
            As[(kk4 + 2) * 129 + r] = v.z;
            As[(kk4 + 3) * 129 + r] = v.w;
        }
        // --- load B tile (16 x 64) ---
        {
            int kk = tid >> 4;                 // 0..15
            int c4 = (tid & 15) << 2;          // 0..60
            *reinterpret_cast<float4*>(Bs + kk * 64 + c4) =
                *reinterpret_cast<const float4*>(
                    Bp + (long long)(k0 + kk) * ldb + col0 + c4);
        }
        __syncthreads();

#pragma unroll
        for (int kk = 0; kk < 16; kk++) {
            float a[8], b[4];
#pragma unroll
            for (int j = 0; j < 8; j++) a[j] = As[kk * 129 + ty * 8 + j];
#pragma unroll
            for (int j = 0; j < 4; j++) b[j] = Bs[kk * 64 + tx * 4 + j];
#pragma unroll
            for (int i = 0; i < 8; i++)
#pragma unroll
                for (int j = 0; j < 4; j++)
                    acc[i][j] += a[i] * b[j];
        }
        __syncthreads();
    }

    const float bv = bias ? bias[(int)(bz & 31)] : 0.0f;
    float* Cp = C + bz * strideC;
    const float* Ap = Cadd ? (Cadd + bz * strideC) : nullptr;

#pragma unroll
    for (int i = 0; i < 8; i++) {
        const int r = row0 + ty * 8 + i;
        const long long off = (long long)r * ldc + col0 + tx * 4;
        float4 v = make_float4(acc[i][0] + bv, acc[i][1] + bv,
                               acc[i][2] + bv, acc[i][3] + bv);
        if (Ap) {
            const float4 u = *reinterpret_cast<const float4*>(Ap + off);
            v.x += u.x; v.y += u.y; v.z += u.z; v.w += u.w;
        }
        *reinterpret_cast<float4*>(Cp + off) = v;
    }
}

// ---------------------------------------------------------------------------
// Elementwise: C[r*ldc + c] = A[idx] + beta * B[idx]   over 1024x1024
// ---------------------------------------------------------------------------
__global__ __launch_bounds__(256) void ew_axpby(
    const float* __restrict__ A, const float* __restrict__ B,
    float* __restrict__ C, float beta, int ldc)
{
    int idx = blockIdx.x * 256 + threadIdx.x;   // 0 .. 1M-1
    int r = idx >> 10;
    int c = idx & 1023;
    C[r * ldc + c] = A[idx] + beta * B[idx];
}

// ---------------------------------------------------------------------------
// Channel mix: for each (b,n,t) compute
//   u_g[o] = sum_c W[o*96 + 32g + c] * x[b,c,n,t]   for g = 0,1,2
// u0 -> g_U0 [b][o][n][t]; u1/u2 -> g_U [b][o][2N][T] rows n and N+n.
// Block: 256 threads = 4 n's x 64 t's. Grid: (N/4, B).
// ---------------------------------------------------------------------------
__global__ __launch_bounds__(256) void chanmix_kernel(
    const float* __restrict__ x, const float* __restrict__ W,
    float* __restrict__ U, float* __restrict__ U0)
{
    __shared__ float Ws[32 * 96];
    const int tid = threadIdx.x;
#pragma unroll
    for (int i = 0; i < 12; i++) Ws[tid + i * 256] = W[tid + i * 256];
    __syncthreads();

    const int t  = tid & 63;
    const int nn = tid >> 6;
    const int n  = blockIdx.x * 4 + nn;
    const int b  = blockIdx.y;

    float xv[32];
    const long long xbase = (((long long)b * 32) * NN + n) * TT + t;
#pragma unroll
    for (int c = 0; c < 32; c++)
        xv[c] = x[xbase + (long long)c * NN * TT];

    for (int o = 0; o < 32; o++) {
        float a0 = 0.f, a1 = 0.f, a2 = 0.f;
        const float* wr = &Ws[o * 96];
#pragma unroll
        for (int c = 0; c < 32; c++) {
            const float xc = xv[c];
            a0 += wr[c]      * xc;
            a1 += wr[32 + c] * xc;
            a2 += wr[64 + c] * xc;
        }
        const long long u0i = (((long long)(b * 32 + o)) * NN + n) * TT + t;
        const long long u1i = (((long long)(b * 32 + o)) * 2 * NN + n) * TT + t;
        U0[u0i]               = a0;
        U [u1i]               = a1;
        U [u1i + NN * TT]     = a2;
    }
}

// ---------------------------------------------------------------------------
// Launch
// ---------------------------------------------------------------------------
extern "C" void kernel_launch(void* const* d_in, const int* in_sizes, int n_in,
                              void* d_out, int out_size)
{
    const float* x  = (const float*)d_in[0];  // [16,32,1024,64]
    const float* AL = (const float*)d_in[1];  // [1024,1024]
    const float* AS = (const float*)d_in[2];  // [1024,1024]
    const float* W  = (const float*)d_in[3];  // [32,96]
    const float* bm = (const float*)d_in[4];  // [32]
    float* out = (float*)d_out;               // [16,32,1024,64]

    float *pU, *pU0, *pM, *pG1, *pG2, *pS;
    cudaGetSymbolAddress((void**)&pU,  g_U);
    cudaGetSymbolAddress((void**)&pU0, g_U0);
    cudaGetSymbolAddress((void**)&pM,  g_M);
    cudaGetSymbolAddress((void**)&pG1, g_G1);
    cudaGetSymbolAddress((void**)&pG2, g_G2);
    cudaGetSymbolAddress((void**)&pS,  g_S);

    const dim3 blk(256);
    const dim3 gpre(NN / 64, NN / 128, 1);

    // --- precompute M1 = AL^2 + AS(I-AL), M2 = AL^3 + AS^2(I-AL) ---
    // G1 = AL @ AL
    gemm_f32_128x64<<<gpre, blk>>>(AL, AL, pG1, 1024, 1024, 1024, 1024, 0, 0, nullptr, nullptr);
    // G2 = AS @ AL
    gemm_f32_128x64<<<gpre, blk>>>(AS, AL, pG2, 1024, 1024, 1024, 1024, 0, 0, nullptr, nullptr);
    // S = AS - G2  ( = AS(I-AL) )
    ew_axpby<<<4096, 256>>>(AS, pG2, pS, -1.0f, 1024);
    // M[:, 0:1024] = G1 + S  ( = M1 )
    ew_axpby<<<4096, 256>>>(pG1, pS, pM, 1.0f, 2 * NN);
    // G2 <- AL @ G1  ( = AL^3 )
    gemm_f32_128x64<<<gpre, blk>>>(AL, pG1, pG2, 1024, 1024, 1024, 1024, 0, 0, nullptr, nullptr);
    // G1 <- AS @ S   ( = AS^2(I-AL) )
    gemm_f32_128x64<<<gpre, blk>>>(AS, pS, pG1, 1024, 1024, 1024, 1024, 0, 0, nullptr, nullptr);
    // M[:, 1024:2048] = G2 + G1  ( = M2 )
    ew_axpby<<<4096, 256>>>(pG2, pG1, pM + NN, 1.0f, 2 * NN);

    // --- channel mix: u0/u1/u2 from x ---
    chanmix_kernel<<<dim3(NN / 4, BB), blk>>>(x, W, pU, pU0);

    // --- main batched GEMM: out[bz] = M @ U[bz] + U0[bz] + bias ---
    const dim3 gmain(1, NN / 128, BB * CC);
    gemm_f32_128x64<<<gmain, blk>>>(pM, pU, out,
                                    2 * NN,          // K
                                    2 * NN, TT, TT,  // lda, ldb, ldc
                                    (long long)2 * NN * TT,  // strideB
                                    (long long)NN * TT,      // strideC
                                    pU0, bm);
}

// round 4
// speedup vs baseline: 2.5744x; 2.5744x over previous
#include <cuda_runtime.h>
#include <cstdint>

// ---------------------------------------------------------------------------
// Problem constants
// ---------------------------------------------------------------------------
#define NN   1024
#define TT   64
#define BB   16
#define KDIM 2048          // 2*NN (M1 | M2 concat)
#define JDIM 32768         // B*C_OUT*T = 512*64

// main mma.sync GEMM tiling
#define BM 256
#define BN 128
#define BK 32
#define STAGES 3
#define MAIN_ITERS (KDIM / BK)          // 64
#define LDA 36                           // BK + 4 pad (floats)
#define LDB 136                          // BN + 8 pad (floats)
#define A_STAGE_BYTES (BM * LDA * 4)     // 36864
#define B_STAGE_BYTES (BK * LDB * 4)     // 17408
#define STAGE_BYTES (A_STAGE_BYTES + B_STAGE_BYTES)   // 54272
#define SMEM_MAIN (STAGES * STAGE_BYTES)               // 162816

// ---------------------------------------------------------------------------
// Scratch (device globals; allocations are forbidden)
// ---------------------------------------------------------------------------
__device__ __align__(128) float g_Uw[(size_t)KDIM * JDIM];  // [k][j] 256MB (tf32-rounded)
__device__ __align__(128) float g_U0[(size_t)NN * JDIM];    // [n][j] 128MB
__device__ __align__(128) float g_M [NN * KDIM];            // [n][k] 8MB (tf32-rounded)
__device__ __align__(128) float g_G1[NN * NN];
__device__ __align__(128) float g_G2[NN * NN];
__device__ __align__(128) float g_S [NN * NN];

// ---------------------------------------------------------------------------
// Helpers
// ---------------------------------------------------------------------------
__device__ __forceinline__ uint32_t smem_u32(const void* p) {
    uint32_t a;
    asm("{ .reg .u64 t; cvta.to.shared.u64 t, %1; cvt.u32.u64 %0, t; }" : "=r"(a) : "l"(p));
    return a;
}
__device__ __forceinline__ float to_tf32(float x) {
    float r; asm("cvt.rna.tf32.f32 %0, %1;" : "=f"(r) : "f"(x)); return r;
}
__device__ __forceinline__ void cp_async16(uint32_t saddr, const void* gaddr) {
    asm volatile("cp.async.cg.shared.global [%0], [%1], 16;" :: "r"(saddr), "l"(gaddr) : "memory");
}
#define CP_COMMIT() asm volatile("cp.async.commit_group;" ::: "memory")
#define CP_WAIT1()  asm volatile("cp.async.wait_group 1;" ::: "memory")

__device__ __forceinline__ void mma_tf32(float* d, const uint32_t* a, const uint32_t* b) {
    asm volatile(
        "mma.sync.aligned.m16n8k8.row.col.f32.tf32.tf32.f32 "
        "{%0,%1,%2,%3}, {%4,%5,%6,%7}, {%8,%9}, {%0,%1,%2,%3};\n"
        : "+f"(d[0]), "+f"(d[1]), "+f"(d[2]), "+f"(d[3])
        : "r"(a[0]), "r"(a[1]), "r"(a[2]), "r"(a[3]), "r"(b[0]), "r"(b[1]));
}

// ---------------------------------------------------------------------------
// fp32 SIMT GEMM for the tiny N^3 precompute
// ---------------------------------------------------------------------------
__global__ __launch_bounds__(256) void gemm_f32_128x64(
    const float* __restrict__ A, const float* __restrict__ B, float* __restrict__ C,
    int K, int lda, int ldb, int ldc)
{
    const int tid  = threadIdx.x;
    const int tx   = tid & 15;
    const int ty   = tid >> 4;
    const int row0 = blockIdx.y * 128;
    const int col0 = blockIdx.x * 64;

    __shared__ float As[16 * 129];
    __shared__ float Bs[16 * 64];

    float acc[8][4];
#pragma unroll
    for (int i = 0; i < 8; i++)
#pragma unroll
        for (int j = 0; j < 4; j++) acc[i][j] = 0.0f;

    for (int k0 = 0; k0 < K; k0 += 16) {
#pragma unroll
        for (int i = 0; i < 2; i++) {
            int vidx = tid + i * 256;
            int r    = vidx >> 2;
            int kk4  = (vidx & 3) << 2;
            const float4 v = *reinterpret_cast<const float4*>(
                A + (long long)(row0 + r) * lda + k0 + kk4);
            As[(kk4 + 0) * 129 + r] = v.x;
            As[(kk4 + 1) * 129 + r] = v.y;
            As[(kk4 + 2) * 129 + r] = v.z;
            As[(kk4 + 3) * 129 + r] = v.w;
        }
        {
            int kk = tid >> 4;
            int c4 = (tid & 15) << 2;
            *reinterpret_cast<float4*>(Bs + kk * 64 + c4) =
                *reinterpret_cast<const float4*>(B + (long long)(k0 + kk) * ldb + col0 + c4);
        }
        __syncthreads();
#pragma unroll
        for (int kk = 0; kk < 16; kk++) {
            float a[8], b[4];
#pragma unroll
            for (int j = 0; j < 8; j++) a[j] = As[kk * 129 + ty * 8 + j];
#pragma unroll
            for (int j = 0; j < 4; j++) b[j] = Bs[kk * 64 + tx * 4 + j];
#pragma unroll
            for (int i = 0; i < 8; i++)
#pragma unroll
                for (int j = 0; j < 4; j++) acc[i][j] += a[i] * b[j];
        }
        __syncthreads();
    }
#pragma unroll
    for (int i = 0; i < 8; i++) {
        const int r = row0 + ty * 8 + i;
        *reinterpret_cast<float4*>(C + (long long)r * ldc + col0 + tx * 4) =
            make_float4(acc[i][0], acc[i][1], acc[i][2], acc[i][3]);
    }
}

// C = A + beta*B over 1024x1024 inputs; optional tf32 rounding of the result
__global__ __launch_bounds__(256) void ew_axpby(
    const float* __restrict__ A, const float* __restrict__ B,
    float* __restrict__ C, float beta, int ldc, int round_tf32)
{
    int idx = blockIdx.x * 256 + threadIdx.x;
    int r = idx >> 10;
    int c = idx & 1023;
    float v = A[idx] + beta * B[idx];
    C[(size_t)r * ldc + c] = round_tf32 ? to_tf32(v) : v;
}

// ---------------------------------------------------------------------------
// Channel mix: u_g[o] = sum_c W[o*96+32g+c] * x[b,c,n,t]
//   g=0 -> U0[n][j] (fp32);  g=1 -> Uw[n][j];  g=2 -> Uw[N+n][j]  (tf32-rounded)
//   j = (b*32+o)*64 + t
// ---------------------------------------------------------------------------
__global__ __launch_bounds__(256) void chanmix_kernel(
    const float* __restrict__ x, const float* __restrict__ W,
    float* __restrict__ Uw, float* __restrict__ U0)
{
    __shared__ float Ws[32 * 96];
    const int tid = threadIdx.x;
#pragma unroll
    for (int i = 0; i < 12; i++) Ws[tid + i * 256] = W[tid + i * 256];
    __syncthreads();

    const int t  = tid & 63;
    const int nn = tid >> 6;
    const int n  = blockIdx.x * 4 + nn;
    const int b  = blockIdx.y;

    float xv[32];
    const size_t xbase = (((size_t)b * 32) * NN + n) * TT + t;
#pragma unroll
    for (int c = 0; c < 32; c++)
        xv[c] = x[xbase + (size_t)c * NN * TT];

    for (int o = 0; o < 32; o++) {
        float a0 = 0.f, a1 = 0.f, a2 = 0.f;
        const float* wr = &Ws[o * 96];
#pragma unroll
        for (int c = 0; c < 32; c++) {
            const float xc = xv[c];
            a0 += wr[c]      * xc;
            a1 += wr[32 + c] * xc;
            a2 += wr[64 + c] * xc;
        }
        const size_t j = ((size_t)(b * 32 + o)) * 64 + t;
        U0[(size_t)n * JDIM + j]        = a0;
        Uw[(size_t)n * JDIM + j]        = to_tf32(a1);
        Uw[(size_t)(NN + n) * JDIM + j] = to_tf32(a2);
    }
}

// ---------------------------------------------------------------------------
// Main GEMM via mma.sync tf32:
//   D[1024 x 32768] = Mmat[1024 x 2048] @ Uw   (Uw stored [k][j])
//   out[bz][n][t] = D[n][j] + U0[n][j] + bias[bz & 31],  bz=j>>6, t=j&63
// CTA tile 256x128, BK=32, 256 threads = 8 warps (4M x 2N), warp tile 64x64.
// ---------------------------------------------------------------------------
__global__ __launch_bounds__(256, 1) void main_gemm_mma(
    const float* __restrict__ Amat, const float* __restrict__ Bmat,
    const float* __restrict__ U0,   const float* __restrict__ bias,
    float* __restrict__ out)
{
    extern __shared__ __align__(1024) char smem[];
    const uint32_t sbase = smem_u32(smem);
    float* smf = reinterpret_cast<float*>(smem);

    const int tid  = threadIdx.x;
    const int wid  = tid >> 5;
    const int lane = tid & 31;
    const int wm   = wid >> 1;     // 0..3
    const int wn   = wid & 1;      // 0..1
    const int qrow = lane >> 2;    // 0..7
    const int qcol = lane & 3;     // 0..3

    const int row0 = blockIdx.x * BM;   // 0..768
    const int col0 = blockIdx.y * BN;   // 0..32640

    float acc[4][8][4];
#pragma unroll
    for (int mt = 0; mt < 4; mt++)
#pragma unroll
        for (int nt = 0; nt < 8; nt++)
#pragma unroll
            for (int q = 0; q < 4; q++) acc[mt][nt][q] = 0.0f;

    // cp.async thread mapping
    const int a_row = tid >> 3;          // base pattern idx = tid + j*256
    const int a_chk = tid & 7;
    const int b_k   = tid >> 5;
    const int b_chk = tid & 31;

    const float* gA = Amat + (size_t)row0 * KDIM;
    const float* gB = Bmat + col0;

#define LOAD_STAGE(it, slot)                                                         \
    do {                                                                             \
        const uint32_t sa = sbase + (slot) * STAGE_BYTES;                            \
        const uint32_t sb = sa + A_STAGE_BYTES;                                      \
        const int koff = (it) * BK;                                                  \
        _Pragma("unroll")                                                            \
        for (int jj = 0; jj < 8; jj++) {                                             \
            const int r = a_row + jj * 32;                                           \
            cp_async16(sa + r * (LDA * 4) + a_chk * 16,                              \
                       gA + (size_t)r * KDIM + koff + a_chk * 4);                    \
        }                                                                            \
        _Pragma("unroll")                                                            \
        for (int jj = 0; jj < 4; jj++) {                                             \
            const int k = b_k + jj * 8;                                              \
            cp_async16(sb + k * (LDB * 4) + b_chk * 16,                              \
                       gB + (size_t)(koff + k) * JDIM + b_chk * 4);                  \
        }                                                                            \
    } while (0)

    // prologue: stages 0,1
    LOAD_STAGE(0, 0); CP_COMMIT();
    LOAD_STAGE(1, 1); CP_COMMIT();

    int slot_c = 0;    // compute slot
    for (int it = 0; it < MAIN_ITERS; ++it) {
        CP_WAIT1();
        __syncthreads();

        if (it + 2 < MAIN_ITERS) {
            int sl = (it + 2) % STAGES;
            LOAD_STAGE(it + 2, sl);
        }
        CP_COMMIT();

        // ---- compute on slot_c ----
        const float* As = smf + slot_c * (STAGE_BYTES / 4);
        const float* Bs = As + (A_STAGE_BYTES / 4);
        const int arow_base = wm * 64 + qrow;
        const int bcol_base = wn * 64 + qrow;
#pragma unroll
        for (int ks = 0; ks < 4; ks++) {
            const int k0 = ks * 8;
            uint32_t af[4][4];
#pragma unroll
            for (int mt = 0; mt < 4; mt++) {
                const float* ap = As + (arow_base + mt * 16) * LDA + k0 + qcol;
                af[mt][0] = __float_as_uint(ap[0]);
                af[mt][1] = __float_as_uint(ap[8 * LDA]);
                af[mt][2] = __float_as_uint(ap[4]);
                af[mt][3] = __float_as_uint(ap[8 * LDA + 4]);
            }
            uint32_t bf[8][2];
#pragma unroll
            for (int nt = 0; nt < 8; nt++) {
                const float* bp = Bs + (k0 + qcol) * LDB + bcol_base + nt * 8;
                bf[nt][0] = __float_as_uint(bp[0]);
                bf[nt][1] = __float_as_uint(bp[4 * LDB]);
            }
#pragma unroll
            for (int mt = 0; mt < 4; mt++)
#pragma unroll
                for (int nt = 0; nt < 8; nt++)
                    mma_tf32(acc[mt][nt], af[mt], bf[nt]);
        }
        slot_c = (slot_c + 1) % STAGES;
    }
#undef LOAD_STAGE

    // ---- epilogue: + U0 + bias, scatter to out[bz][n][t] ----
    const int j0 = col0 + wn * 64;       // 64-aligned => single bz per warp
    const int bz = j0 >> 6;
    const float bv = bias[bz & 31];
#pragma unroll
    for (int mt = 0; mt < 4; mt++) {
#pragma unroll
        for (int h = 0; h < 2; h++) {
            const int n = row0 + wm * 64 + mt * 16 + h * 8 + qrow;
            float* orow = out + (size_t)bz * (NN * TT) + (size_t)n * TT;
            const float* u0row = U0 + (size_t)n * JDIM + j0;
#pragma unroll
            for (int nt = 0; nt < 8; nt++) {
                const int t = nt * 8 + qcol * 2;
                const float2 u = *reinterpret_cast<const float2*>(u0row + t);
                float2 v;
                v.x = acc[mt][nt][h * 2 + 0] + u.x + bv;
                v.y = acc[mt][nt][h * 2 + 1] + u.y + bv;
                *reinterpret_cast<float2*>(orow + t) = v;
            }
        }
    }
}

// ---------------------------------------------------------------------------
// Launch
// ---------------------------------------------------------------------------
extern "C" void kernel_launch(void* const* d_in, const int* in_sizes, int n_in,
                              void* d_out, int out_size)
{
    const float* x  = (const float*)d_in[0];
    const float* AL = (const float*)d_in[1];
    const float* AS = (const float*)d_in[2];
    const float* W  = (const float*)d_in[3];
    const float* bm = (const float*)d_in[4];
    float* out = (float*)d_out;

    float *pUw, *pU0, *pM, *pG1, *pG2, *pS;
    cudaGetSymbolAddress((void**)&pUw, g_Uw);
    cudaGetSymbolAddress((void**)&pU0, g_U0);
    cudaGetSymbolAddress((void**)&pM,  g_M);
    cudaGetSymbolAddress((void**)&pG1, g_G1);
    cudaGetSymbolAddress((void**)&pG2, g_G2);
    cudaGetSymbolAddress((void**)&pS,  g_S);

    cudaFuncSetAttribute(main_gemm_mma,
                         cudaFuncAttributeMaxDynamicSharedMemorySize, SMEM_MAIN);

    const dim3 blk(256);
    const dim3 gpre(NN / 64, NN / 128, 1);

    // M1 = AL^2 + AS(I-AL), M2 = AL^3 + AS^2(I-AL)  (fp32; final writes tf32-rounded)
    gemm_f32_128x64<<<gpre, blk>>>(AL, AL, pG1, 1024, 1024, 1024, 1024);  // G1 = AL^2
    gemm_f32_128x64<<<gpre, blk>>>(AS, AL, pG2, 1024, 1024, 1024, 1024);  // G2 = AS*AL
    ew_axpby<<<4096, 256>>>(AS, pG2, pS, -1.0f, 1024, 0);                 // S = AS - AS*AL
    ew_axpby<<<4096, 256>>>(pG1, pS, pM, 1.0f, KDIM, 1);                  // M[:,0:1024] = M1 (tf32)
    gemm_f32_128x64<<<gpre, blk>>>(AL, pG1, pG2, 1024, 1024, 1024, 1024); // G2 = AL^3
    gemm_f32_128x64<<<gpre, blk>>>(AS, pS, pG1, 1024, 1024, 1024, 1024);  // G1 = AS^2(I-AL)
    ew_axpby<<<4096, 256>>>(pG2, pG1, pM + NN, 1.0f, KDIM, 1);            // M[:,1024:] = M2 (tf32)

    // channel mix (writes Uw [k][j] and U0 [n][j] directly; no transpose)
    chanmix_kernel<<<dim3(NN / 4, BB), blk>>>(x, W, pUw, pU0);

    // main tensor-core GEMM + fused epilogue
    // grid.x = row tiles (fast) so concurrent CTAs share the same B col tiles
    main_gemm_mma<<<dim3(NN / BM, JDIM / BN), 256, SMEM_MAIN>>>(pM, pUw, pU0, bm, out);
}

// round 5
// speedup vs baseline: 2.5817x; 1.0028x over previous
#include <cuda_runtime.h>
#include <cstdint>

// ---------------------------------------------------------------------------
// Problem constants
// ---------------------------------------------------------------------------
#define NN   1024
#define TT   64
#define BB   16
#define KDIM 2048          // 2*NN (M1 | M2 concat)
#define JDIM 32768         // B*C_OUT*T = 512*64

// main mma.sync GEMM tiling
#define BM 256
#define BN 128
#define BK 32
#define STAGES 3
#define MAIN_ITERS (KDIM / BK)          // 64
#define LDA 36                           // BK + 4 pad (floats)
#define LDB 136                          // BN + 8 pad (floats)
#define A_STAGE_BYTES (BM * LDA * 4)     // 36864
#define B_STAGE_BYTES (BK * LDB * 4)     // 17408
#define STAGE_BYTES (A_STAGE_BYTES + B_STAGE_BYTES)   // 54272
#define SMEM_MAIN (STAGES * STAGE_BYTES)               // 162816

// ---------------------------------------------------------------------------
// Scratch (device globals; allocations are forbidden)
// ---------------------------------------------------------------------------
__device__ __align__(128) float g_Uw[(size_t)KDIM * JDIM];  // [k][j] 256MB (tf32-rounded)
__device__ __align__(128) float g_U0[(size_t)NN * JDIM];    // [n][j] 128MB
__device__ __align__(128) float g_M [NN * KDIM];            // [n][k] 8MB (tf32-rounded)
__device__ __align__(128) float g_G1[NN * NN];
__device__ __align__(128) float g_G2[NN * NN];
__device__ __align__(128) float g_S [NN * NN];

// ---------------------------------------------------------------------------
// Helpers
// ---------------------------------------------------------------------------
__device__ __forceinline__ uint32_t smem_u32(const void* p) {
    uint32_t a;
    asm("{ .reg .u64 t; cvta.to.shared.u64 t, %1; cvt.u32.u64 %0, t; }" : "=r"(a) : "l"(p));
    return a;
}
__device__ __forceinline__ float to_tf32(float x) {
    float r; asm("cvt.rna.tf32.f32 %0, %1;" : "=f"(r) : "f"(x)); return r;
}
__device__ __forceinline__ void cp_async16(uint32_t saddr, const void* gaddr) {
    asm volatile("cp.async.cg.shared.global [%0], [%1], 16;" :: "r"(saddr), "l"(gaddr) : "memory");
}
#define CP_COMMIT() asm volatile("cp.async.commit_group;" ::: "memory")
#define CP_WAIT1()  asm volatile("cp.async.wait_group 1;" ::: "memory")

__device__ __forceinline__ void mma_tf32(float* d, const uint32_t* a, const uint32_t* b) {
    asm volatile(
        "mma.sync.aligned.m16n8k8.row.col.f32.tf32.tf32.f32 "
        "{%0,%1,%2,%3}, {%4,%5,%6,%7}, {%8,%9}, {%0,%1,%2,%3};\n"
        : "+f"(d[0]), "+f"(d[1]), "+f"(d[2]), "+f"(d[3])
        : "r"(a[0]), "r"(a[1]), "r"(a[2]), "r"(a[3]), "r"(b[0]), "r"(b[1]));
}

// ---------------------------------------------------------------------------
// fp32 SIMT GEMM for the tiny N^3 precompute
// ---------------------------------------------------------------------------
__global__ __launch_bounds__(256) void gemm_f32_128x64(
    const float* __restrict__ A, const float* __restrict__ B, float* __restrict__ C,
    int K, int lda, int ldb, int ldc)
{
    const int tid  = threadIdx.x;
    const int tx   = tid & 15;
    const int ty   = tid >> 4;
    const int row0 = blockIdx.y * 128;
    const int col0 = blockIdx.x * 64;

    __shared__ float As[16 * 129];
    __shared__ float Bs[16 * 64];

    float acc[8][4];
#pragma unroll
    for (int i = 0; i < 8; i++)
#pragma unroll
        for (int j = 0; j < 4; j++) acc[i][j] = 0.0f;

    for (int k0 = 0; k0 < K; k0 += 16) {
#pragma unroll
        for (int i = 0; i < 2; i++) {
            int vidx = tid + i * 256;
            int r    = vidx >> 2;
            int kk4  = (vidx & 3) << 2;
            const float4 v = *reinterpret_cast<const float4*>(
                A + (long long)(row0 + r) * lda + k0 + kk4);
            As[(kk4 + 0) * 129 + r] = v.x;
            As[(kk4 + 1) * 129 + r] = v.y;
            As[(kk4 + 2) * 129 + r] = v.z;
            As[(kk4 + 3) * 129 + r] = v.w;
        }
        {
            int kk = tid >> 4;
            int c4 = (tid & 15) << 2;
            *reinterpret_cast<float4*>(Bs + kk * 64 + c4) =
                *reinterpret_cast<const float4*>(B + (long long)(k0 + kk) * ldb + col0 + c4);
        }
        __syncthreads();
#pragma unroll
        for (int kk = 0; kk < 16; kk++) {
            float a[8], b[4];
#pragma unroll
            for (int j = 0; j < 8; j++) a[j] = As[kk * 129 + ty * 8 + j];
#pragma unroll
            for (int j = 0; j < 4; j++) b[j] = Bs[kk * 64 + tx * 4 + j];
#pragma unroll
            for (int i = 0; i < 8; i++)
#pragma unroll
                for (int j = 0; j < 4; j++) acc[i][j] += a[i] * b[j];
        }
        __syncthreads();
    }
#pragma unroll
    for (int i = 0; i < 8; i++) {
        const int r = row0 + ty * 8 + i;
        *reinterpret_cast<float4*>(C + (long long)r * ldc + col0 + tx * 4) =
            make_float4(acc[i][0], acc[i][1], acc[i][2], acc[i][3]);
    }
}

// C = A + beta*B over 1024x1024 inputs; optional tf32 rounding of the result
__global__ __launch_bounds__(256) void ew_axpby(
    const float* __restrict__ A, const float* __restrict__ B,
    float* __restrict__ C, float beta, int ldc, int round_tf32)
{
    int idx = blockIdx.x * 256 + threadIdx.x;
    int r = idx >> 10;
    int c = idx & 1023;
    float v = A[idx] + beta * B[idx];
    C[(size_t)r * ldc + c] = round_tf32 ? to_tf32(v) : v;
}

// ---------------------------------------------------------------------------
// Channel mix: u_g[o] = sum_c W[o*96+32g+c] * x[b,c,n,t]
//   g=0 -> U0[n][j] (fp32);  g=1 -> Uw[n][j];  g=2 -> Uw[N+n][j]  (tf32-rounded)
//   j = (b*32+o)*64 + t
// ---------------------------------------------------------------------------
__global__ __launch_bounds__(256) void chanmix_kernel(
    const float* __restrict__ x, const float* __restrict__ W,
    float* __restrict__ Uw, float* __restrict__ U0)
{
    __shared__ float Ws[32 * 96];
    const int tid = threadIdx.x;
#pragma unroll
    for (int i = 0; i < 12; i++) Ws[tid + i * 256] = W[tid + i * 256];
    __syncthreads();

    const int t  = tid & 63;
    const int nn = tid >> 6;
    const int n  = blockIdx.x * 4 + nn;
    const int b  = blockIdx.y;

    float xv[32];
    const size_t xbase = (((size_t)b * 32) * NN + n) * TT + t;
#pragma unroll
    for (int c = 0; c < 32; c++)
        xv[c] = x[xbase + (size_t)c * NN * TT];

    for (int o = 0; o < 32; o++) {
        float a0 = 0.f, a1 = 0.f, a2 = 0.f;
        const float* wr = &Ws[o * 96];
#pragma unroll
        for (int c = 0; c < 32; c++) {
            const float xc = xv[c];
            a0 += wr[c]      * xc;
            a1 += wr[32 + c] * xc;
            a2 += wr[64 + c] * xc;
        }
        const size_t j = ((size_t)(b * 32 + o)) * 64 + t;
        U0[(size_t)n * JDIM + j]        = a0;
        Uw[(size_t)n * JDIM + j]        = to_tf32(a1);
        Uw[(size_t)(NN + n) * JDIM + j] = to_tf32(a2);
    }
}

// ---------------------------------------------------------------------------
// Main GEMM via mma.sync tf32:
//   D[1024 x 32768] = Mmat[1024 x 2048] @ Uw   (Uw stored [k][j])
//   out[bz][n][t] = D[n][j] + U0[n][j] + bias[bz & 31],  bz=j>>6, t=j&63
// CTA tile 256x128, BK=32, 256 threads = 8 warps (4M x 2N), warp tile 64x64.
// ---------------------------------------------------------------------------
__global__ __launch_bounds__(256, 1) void main_gemm_mma(
    const float* __restrict__ Amat, const float* __restrict__ Bmat,
    const float* __restrict__ U0,   const float* __restrict__ bias,
    float* __restrict__ out)
{
    extern __shared__ __align__(1024) char smem[];
    const uint32_t sbase = smem_u32(smem);
    float* smf = reinterpret_cast<float*>(smem);

    const int tid  = threadIdx.x;
    const int wid  = tid >> 5;
    const int lane = tid & 31;
    const int wm   = wid >> 1;     // 0..3
    const int wn   = wid & 1;      // 0..1
    const int qrow = lane >> 2;    // 0..7
    const int qcol = lane & 3;     // 0..3

    const int row0 = blockIdx.x * BM;   // 0..768
    const int col0 = blockIdx.y * BN;   // 0..32640

    float acc[4][8][4];
#pragma unroll
    for (int mt = 0; mt < 4; mt++)
#pragma unroll
        for (int nt = 0; nt < 8; nt++)
#pragma unroll
            for (int q = 0; q < 4; q++) acc[mt][nt][q] = 0.0f;

    // cp.async thread mapping
    const int a_row = tid >> 3;          // base pattern idx = tid + j*256
    const int a_chk = tid & 7;
    const int b_k   = tid >> 5;
    const int b_chk = tid & 31;

    const float* gA = Amat + (size_t)row0 * KDIM;
    const float* gB = Bmat + col0;

#define LOAD_STAGE(it, slot)                                                         \
    do {                                                                             \
        const uint32_t sa = sbase + (slot) * STAGE_BYTES;                            \
        const uint32_t sb = sa + A_STAGE_BYTES;                                      \
        const int koff = (it) * BK;                                                  \
        _Pragma("unroll")                                                            \
        for (int jj = 0; jj < 8; jj++) {                                             \
            const int r = a_row + jj * 32;                                           \
            cp_async16(sa + r * (LDA * 4) + a_chk * 16,                              \
                       gA + (size_t)r * KDIM + koff + a_chk * 4);                    \
        }                                                                            \
        _Pragma("unroll")                                                            \
        for (int jj = 0; jj < 4; jj++) {                                             \
            const int k = b_k + jj * 8;                                              \
            cp_async16(sb + k * (LDB * 4) + b_chk * 16,                              \
                       gB + (size_t)(koff + k) * JDIM + b_chk * 4);                  \
        }                                                                            \
    } while (0)

    // prologue: stages 0,1
    LOAD_STAGE(0, 0); CP_COMMIT();
    LOAD_STAGE(1, 1); CP_COMMIT();

    int slot_c = 0;    // compute slot
    for (int it = 0; it < MAIN_ITERS; ++it) {
        CP_WAIT1();
        __syncthreads();

        if (it + 2 < MAIN_ITERS) {
            int sl = (it + 2) % STAGES;
            LOAD_STAGE(it + 2, sl);
        }
        CP_COMMIT();

        // ---- compute on slot_c ----
        const float* As = smf + slot_c * (STAGE_BYTES / 4);
        const float* Bs = As + (A_STAGE_BYTES / 4);
        const int arow_base = wm * 64 + qrow;
        const int bcol_base = wn * 64 + qrow;
#pragma unroll
        for (int ks = 0; ks < 4; ks++) {
            const int k0 = ks * 8;
            uint32_t af[4][4];
#pragma unroll
            for (int mt = 0; mt < 4; mt++) {
                const float* ap = As + (arow_base + mt * 16) * LDA + k0 + qcol;
                af[mt][0] = __float_as_uint(ap[0]);
                af[mt][1] = __float_as_uint(ap[8 * LDA]);
                af[mt][2] = __float_as_uint(ap[4]);
                af[mt][3] = __float_as_uint(ap[8 * LDA + 4]);
            }
            uint32_t bf[8][2];
#pragma unroll
            for (int nt = 0; nt < 8; nt++) {
                const float* bp = Bs + (k0 + qcol) * LDB + bcol_base + nt * 8;
                bf[nt][0] = __float_as_uint(bp[0]);
                bf[nt][1] = __float_as_uint(bp[4 * LDB]);
            }
#pragma unroll
            for (int mt = 0; mt < 4; mt++)
#pragma unroll
                for (int nt = 0; nt < 8; nt++)
                    mma_tf32(acc[mt][nt], af[mt], bf[nt]);
        }
        slot_c = (slot_c + 1) % STAGES;
    }
#undef LOAD_STAGE

    // ---- epilogue: + U0 + bias, scatter to out[bz][n][t] ----
    const int j0 = col0 + wn * 64;       // 64-aligned => single bz per warp
    const int bz = j0 >> 6;
    const float bv = bias[bz & 31];
#pragma unroll
    for (int mt = 0; mt < 4; mt++) {
#pragma unroll
        for (int h = 0; h < 2; h++) {
            const int n = row0 + wm * 64 + mt * 16 + h * 8 + qrow;
            float* orow = out + (size_t)bz * (NN * TT) + (size_t)n * TT;
            const float* u0row = U0 + (size_t)n * JDIM + j0;
#pragma unroll
            for (int nt = 0; nt < 8; nt++) {
                const int t = nt * 8 + qcol * 2;
                const float2 u = *reinterpret_cast<const float2*>(u0row + t);
                float2 v;
                v.x = acc[mt][nt][h * 2 + 0] + u.x + bv;
                v.y = acc[mt][nt][h * 2 + 1] + u.y + bv;
                *reinterpret_cast<float2*>(orow + t) = v;
            }
        }
    }
}

// ---------------------------------------------------------------------------
// Launch
// ---------------------------------------------------------------------------
extern "C" void kernel_launch(void* const* d_in, const int* in_sizes, int n_in,
                              void* d_out, int out_size)
{
    const float* x  = (const float*)d_in[0];
    const float* AL = (const float*)d_in[1];
    const float* AS = (const float*)d_in[2];
    const float* W  = (const float*)d_in[3];
    const float* bm = (const float*)d_in[4];
    float* out = (float*)d_out;

    float *pUw, *pU0, *pM, *pG1, *pG2, *pS;
    cudaGetSymbolAddress((void**)&pUw, g_Uw);
    cudaGetSymbolAddress((void**)&pU0, g_U0);
    cudaGetSymbolAddress((void**)&pM,  g_M);
    cudaGetSymbolAddress((void**)&pG1, g_G1);
    cudaGetSymbolAddress((void**)&pG2, g_G2);
    cudaGetSymbolAddress((void**)&pS,  g_S);

    cudaFuncSetAttribute(main_gemm_mma,
                         cudaFuncAttributeMaxDynamicSharedMemorySize, SMEM_MAIN);

    const dim3 blk(256);
    const dim3 gpre(NN / 64, NN / 128, 1);

    // M1 = AL^2 + AS(I-AL), M2 = AL^3 + AS^2(I-AL)  (fp32; final writes tf32-rounded)
    gemm_f32_128x64<<<gpre, blk>>>(AL, AL, pG1, 1024, 1024, 1024, 1024);  // G1 = AL^2
    gemm_f32_128x64<<<gpre, blk>>>(AS, AL, pG2, 1024, 1024, 1024, 1024);  // G2 = AS*AL
    ew_axpby<<<4096, 256>>>(AS, pG2, pS, -1.0f, 1024, 0);                 // S = AS - AS*AL
    ew_axpby<<<4096, 256>>>(pG1, pS, pM, 1.0f, KDIM, 1);                  // M[:,0:1024] = M1 (tf32)
    gemm_f32_128x64<<<gpre, blk>>>(AL, pG1, pG2, 1024, 1024, 1024, 1024); // G2 = AL^3
    gemm_f32_128x64<<<gpre, blk>>>(AS, pS, pG1, 1024, 1024, 1024, 1024);  // G1 = AS^2(I-AL)
    ew_axpby<<<4096, 256>>>(pG2, pG1, pM + NN, 1.0f, KDIM, 1);            // M[:,1024:] = M2 (tf32)

    // channel mix (writes Uw [k][j] and U0 [n][j] directly; no transpose)
    chanmix_kernel<<<dim3(NN / 4, BB), blk>>>(x, W, pUw, pU0);

    // main tensor-core GEMM + fused epilogue
    // grid.x = row tiles (fast) so concurrent CTAs share the same B col tiles
    main_gemm_mma<<<dim3(NN / BM, JDIM / BN), 256, SMEM_MAIN>>>(pM, pUw, pU0, bm, out);
}

// round 6
// speedup vs baseline: 4.7005x; 1.8207x over previous
#include <cuda_runtime.h>
#include <cuda_bf16.h>
#include <cstdint>

// ---------------------------------------------------------------------------
// Problem constants
// ---------------------------------------------------------------------------
#define NN   1024
#define TT   64
#define BB   16
#define KDIM 2048          // 2*NN (M1|M2 interleaved as k'=2m / 2m+1)
#define JDIM 32768         // B*C_OUT*T = 512*64

// shared GEMM tiling (both kernels): CTA 256x128, 256 thr, 8 warps (4M x 2N)
#define BM 256
#define BN 128
#define LDAW 36                          // uint32 per A smem row (32 data + 4 pad)
#define LDBW 136                         // uint32 per B smem row (128 data + 8 pad)
#define A_STAGE_BYTES (BM * LDAW * 4)    // 36864
#define B_STAGE_BYTES (32 * LDBW * 4)    // 17408
#define STAGE_BYTES (A_STAGE_BYTES + B_STAGE_BYTES)   // 54272
#define SMEM_GEMM (3 * STAGE_BYTES)                    // 162816
#define GEMM_ITERS 32    // pre: K=1024/BK32 ; main: K=2048/BK64(bf16)

// ---------------------------------------------------------------------------
// Scratch (device globals; allocations are forbidden)
// ---------------------------------------------------------------------------
__device__ __align__(128) uint32_t g_Uw2[(size_t)NN * JDIM]; // [m][j] bf16x2 (u1,u2)  128MB
__device__ __align__(128) float    g_U0 [(size_t)NN * JDIM]; // [n][j] fp32            128MB
__device__ __align__(128) uint32_t g_M2 [NN * NN];           // [n][m] bf16x2 (M1,M2)  4MB
__device__ __align__(128) float g_ALr[NN * NN];
__device__ __align__(128) float g_ASr[NN * NN];
__device__ __align__(128) float g_G1 [NN * NN];
__device__ __align__(128) float g_G2 [NN * NN];   // reused as G2p in stage 2
__device__ __align__(128) float g_S  [NN * NN];
__device__ __align__(128) float g_G1p[NN * NN];

// ---------------------------------------------------------------------------
// Helpers
// ---------------------------------------------------------------------------
__device__ __forceinline__ uint32_t smem_u32(const void* p) {
    uint32_t a;
    asm("{ .reg .u64 t; cvta.to.shared.u64 t, %1; cvt.u32.u64 %0, t; }" : "=r"(a) : "l"(p));
    return a;
}
__device__ __forceinline__ float to_tf32(float x) {
    float r; asm("cvt.rna.tf32.f32 %0, %1;" : "=f"(r) : "f"(x)); return r;
}
__device__ __forceinline__ void cp_async16(uint32_t saddr, const void* gaddr) {
    asm volatile("cp.async.cg.shared.global [%0], [%1], 16;" :: "r"(saddr), "l"(gaddr) : "memory");
}
#define CP_COMMIT() asm volatile("cp.async.commit_group;" ::: "memory")
#define CP_WAIT1()  asm volatile("cp.async.wait_group 1;" ::: "memory")

__device__ __forceinline__ void mma_tf32(float* d, const uint32_t* a, const uint32_t* b) {
    asm volatile(
        "mma.sync.aligned.m16n8k8.row.col.f32.tf32.tf32.f32 "
        "{%0,%1,%2,%3}, {%4,%5,%6,%7}, {%8,%9}, {%0,%1,%2,%3};\n"
        : "+f"(d[0]), "+f"(d[1]), "+f"(d[2]), "+f"(d[3])
        : "r"(a[0]), "r"(a[1]), "r"(a[2]), "r"(a[3]), "r"(b[0]), "r"(b[1]));
}
__device__ __forceinline__ void mma_bf16(float* d, const uint32_t* a, const uint32_t* b) {
    asm volatile(
        "mma.sync.aligned.m16n8k16.row.col.f32.bf16.bf16.f32 "
        "{%0,%1,%2,%3}, {%4,%5,%6,%7}, {%8,%9}, {%0,%1,%2,%3};\n"
        : "+f"(d[0]), "+f"(d[1]), "+f"(d[2]), "+f"(d[3])
        : "r"(a[0]), "r"(a[1]), "r"(a[2]), "r"(a[3]), "r"(b[0]), "r"(b[1]));
}

// ---------------------------------------------------------------------------
// Elementwise kernels (1024x1024 = 1M elements, grid 4096 x 256)
// ---------------------------------------------------------------------------
__global__ __launch_bounds__(256) void ew_tf32copy(
    const float* __restrict__ in, float* __restrict__ out)
{
    int idx = blockIdx.x * 256 + threadIdx.x;
    out[idx] = to_tf32(in[idx]);
}
// C = tf32(A + beta*B)
__global__ __launch_bounds__(256) void ew_axpby_r(
    const float* __restrict__ A, const float* __restrict__ B,
    float* __restrict__ C, float beta)
{
    int idx = blockIdx.x * 256 + threadIdx.x;
    C[idx] = to_tf32(A[idx] + beta * B[idx]);
}
// M2d[idx] = bf16x2( X1+Y1 , X2+Y2 )   (lo = M1, hi = M2)
__global__ __launch_bounds__(256) void ew_buildM(
    const float* __restrict__ X1, const float* __restrict__ Y1,
    const float* __restrict__ X2, const float* __restrict__ Y2,
    uint32_t* __restrict__ M2d)
{
    int idx = blockIdx.x * 256 + threadIdx.x;
    __nv_bfloat162 v = __floats2bfloat162_rn(X1[idx] + Y1[idx], X2[idx] + Y2[idx]);
    M2d[idx] = *reinterpret_cast<uint32_t*>(&v);
}

// ---------------------------------------------------------------------------
// Precompute GEMM (tf32 mma, fp32 in/out, inputs pre-rounded to tf32):
//   C[z][1024x1024] = A[z] @ B[z],  z = blockIdx.z in {0,1}
// BK=32 fp32. Optional tf32 rounding of output.
// ---------------------------------------------------------------------------
__global__ __launch_bounds__(256, 1) void gemm_pre_tf32(
    const float* __restrict__ A0, const float* __restrict__ A1,
    const float* __restrict__ B0, const float* __restrict__ B1,
    float* __restrict__ C0, float* __restrict__ C1, int round_out)
{
    extern __shared__ __align__(1024) char smem[];
    const uint32_t sbase = smem_u32(smem);
    float* smf = reinterpret_cast<float*>(smem);

    const int tid  = threadIdx.x;
    const int wid  = tid >> 5;
    const int lane = tid & 31;
    const int wm   = wid >> 1;
    const int wn   = wid & 1;
    const int qrow = lane >> 2;
    const int qcol = lane & 3;

    const int row0 = blockIdx.x * BM;
    const int col0 = blockIdx.y * BN;
    const float* gA = (blockIdx.z ? A1 : A0) + (size_t)row0 * 1024;
    const float* gB = (blockIdx.z ? B1 : B0) + col0;
    float* gC = (blockIdx.z ? C1 : C0);

    float acc[4][8][4];
#pragma unroll
    for (int mt = 0; mt < 4; mt++)
#pragma unroll
        for (int nt = 0; nt < 8; nt++)
#pragma unroll
            for (int q = 0; q < 4; q++) acc[mt][nt][q] = 0.0f;

    const int a_row = tid >> 3;
    const int a_chk = tid & 7;    // 8 x 16B = 128B = 32 floats (BK)
    const int b_k   = tid >> 5;
    const int b_chk = tid & 31;   // 32 x 16B = 512B = 128 floats (BN)

#define PRE_LOAD(it, slot)                                                           \
    do {                                                                             \
        const uint32_t sa = sbase + (slot) * STAGE_BYTES;                            \
        const uint32_t sb = sa + A_STAGE_BYTES;                                      \
        const int koff = (it) * 32;                                                  \
        _Pragma("unroll")                                                            \
        for (int jj = 0; jj < 8; jj++) {                                             \
            const int r = a_row + jj * 32;                                           \
            cp_async16(sa + r * (LDAW * 4) + a_chk * 16,                             \
                       gA + (size_t)r * 1024 + koff + a_chk * 4);                    \
        }                                                                            \
        _Pragma("unroll")                                                            \
        for (int jj = 0; jj < 4; jj++) {                                             \
            const int k = b_k + jj * 8;                                              \
            cp_async16(sb + k * (LDBW * 4) + b_chk * 16,                             \
                       gB + (size_t)(koff + k) * 1024 + b_chk * 4);                  \
        }                                                                            \
    } while (0)

    PRE_LOAD(0, 0); CP_COMMIT();
    PRE_LOAD(1, 1); CP_COMMIT();

    int slot_c = 0;
    for (int it = 0; it < GEMM_ITERS; ++it) {
        CP_WAIT1();
        __syncthreads();
        if (it + 2 < GEMM_ITERS) PRE_LOAD(it + 2, (it + 2) % 3);
        CP_COMMIT();

        const float* As = smf + slot_c * (STAGE_BYTES / 4);
        const float* Bs = As + (A_STAGE_BYTES / 4);
        const int arow_base = wm * 64 + qrow;
        const int bcol_base = wn * 64 + qrow;
#pragma unroll
        for (int ks = 0; ks < 4; ks++) {
            const int k0 = ks * 8;
            uint32_t af[4][4];
#pragma unroll
            for (int mt = 0; mt < 4; mt++) {
                const float* ap = As + (arow_base + mt * 16) * LDAW + k0 + qcol;
                af[mt][0] = __float_as_uint(ap[0]);
                af[mt][1] = __float_as_uint(ap[8 * LDAW]);
                af[mt][2] = __float_as_uint(ap[4]);
                af[mt][3] = __float_as_uint(ap[8 * LDAW + 4]);
            }
            uint32_t bf[8][2];
#pragma unroll
            for (int nt = 0; nt < 8; nt++) {
                const float* bp = Bs + (k0 + qcol) * LDBW + bcol_base + nt * 8;
                bf[nt][0] = __float_as_uint(bp[0]);
                bf[nt][1] = __float_as_uint(bp[4 * LDBW]);
            }
#pragma unroll
            for (int mt = 0; mt < 4; mt++)
#pragma unroll
                for (int nt = 0; nt < 8; nt++)
                    mma_tf32(acc[mt][nt], af[mt], bf[nt]);
        }
        slot_c = (slot_c + 1) % 3;
    }
#undef PRE_LOAD

#pragma unroll
    for (int mt = 0; mt < 4; mt++) {
#pragma unroll
        for (int h = 0; h < 2; h++) {
            const int n = row0 + wm * 64 + mt * 16 + h * 8 + qrow;
            float* crow = gC + (size_t)n * 1024 + col0 + wn * 64;
#pragma unroll
            for (int nt = 0; nt < 8; nt++) {
                float vx = acc[mt][nt][h * 2 + 0];
                float vy = acc[mt][nt][h * 2 + 1];
                if (round_out) { vx = to_tf32(vx); vy = to_tf32(vy); }
                *reinterpret_cast<float2*>(crow + nt * 8 + qcol * 2) = make_float2(vx, vy);
            }
        }
    }
}

// ---------------------------------------------------------------------------
// Channel mix: u_g[o] = sum_c W[o*96+32g+c] * x[b,c,n,t]
//   g=0 -> U0[n][j] fp32;  (g=1,g=2) -> Uw2[n][j] packed bf16x2 (lo=u1, hi=u2)
//   j = (b*32+o)*64 + t
// ---------------------------------------------------------------------------
__global__ __launch_bounds__(256) void chanmix_kernel(
    const float* __restrict__ x, const float* __restrict__ W,
    uint32_t* __restrict__ Uw2, float* __restrict__ U0)
{
    __shared__ float Ws[32 * 96];
    const int tid = threadIdx.x;
#pragma unroll
    for (int i = 0; i < 12; i++) Ws[tid + i * 256] = W[tid + i * 256];
    __syncthreads();

    const int t  = tid & 63;
    const int nn = tid >> 6;
    const int n  = blockIdx.x * 4 + nn;
    const int b  = blockIdx.y;

    float xv[32];
    const size_t xbase = (((size_t)b * 32) * NN + n) * TT + t;
#pragma unroll
    for (int c = 0; c < 32; c++)
        xv[c] = x[xbase + (size_t)c * NN * TT];

    for (int o = 0; o < 32; o++) {
        float a0 = 0.f, a1 = 0.f, a2 = 0.f;
        const float* wr = &Ws[o * 96];
#pragma unroll
        for (int c = 0; c < 32; c++) {
            const float xc = xv[c];
            a0 += wr[c]      * xc;
            a1 += wr[32 + c] * xc;
            a2 += wr[64 + c] * xc;
        }
        const size_t j = ((size_t)(b * 32 + o)) * 64 + t;
        U0[(size_t)n * JDIM + j] = a0;
        __nv_bfloat162 p = __floats2bfloat162_rn(a1, a2);
        Uw2[(size_t)n * JDIM + j] = *reinterpret_cast<uint32_t*>(&p);
    }
}

// ---------------------------------------------------------------------------
// Main GEMM (bf16 mma m16n8k16):
//   D[1024 x 32768] = Mb[1024 x 2048 bf16] @ U  (U packed as bf16x2 pair rows)
//   out[bz][n][t] = D[n][j] + U0[n][j] + bias[bz & 31]
// CTA 256x128, BK=64 bf16 (=32 pair rows), 3-stage cp.async pipeline.
// ---------------------------------------------------------------------------
__global__ __launch_bounds__(256, 1) void main_gemm_bf16(
    const uint32_t* __restrict__ Mb2, const uint32_t* __restrict__ Uw2,
    const float* __restrict__ U0,     const float* __restrict__ bias,
    float* __restrict__ out)
{
    extern __shared__ __align__(1024) char smem[];
    const uint32_t sbase = smem_u32(smem);
    const uint32_t* smu = reinterpret_cast<uint32_t*>(smem);

    const int tid  = threadIdx.x;
    const int wid  = tid >> 5;
    const int lane = tid & 31;
    const int wm   = wid >> 1;
    const int wn   = wid & 1;
    const int qrow = lane >> 2;
    const int qcol = lane & 3;

    const int row0 = blockIdx.x * BM;
    const int col0 = blockIdx.y * BN;

    float acc[4][8][4];
#pragma unroll
    for (int mt = 0; mt < 4; mt++)
#pragma unroll
        for (int nt = 0; nt < 8; nt++)
#pragma unroll
            for (int q = 0; q < 4; q++) acc[mt][nt][q] = 0.0f;

    const int a_row = tid >> 3;
    const int a_chk = tid & 7;    // 8 x 16B = 128B = 64 bf16 (BK)
    const int b_k   = tid >> 5;
    const int b_chk = tid & 31;   // 32 x 16B = 512B = 128 uint32 (BN)

    const char* gA = (const char*)Mb2 + (size_t)row0 * (NN * 4);  // M row = 1024 uint32 = 4096B
    const uint32_t* gB = Uw2 + col0;

#define MAIN_LOAD(it, slot)                                                          \
    do {                                                                             \
        const uint32_t sa = sbase + (slot) * STAGE_BYTES;                            \
        const uint32_t sb = sa + A_STAGE_BYTES;                                      \
        _Pragma("unroll")                                                            \
        for (int jj = 0; jj < 8; jj++) {                                             \
            const int r = a_row + jj * 32;                                           \
            cp_async16(sa + r * (LDAW * 4) + a_chk * 16,                             \
                       gA + (size_t)r * (NN * 4) + (it) * 128 + a_chk * 16);         \
        }                                                                            \
        _Pragma("unroll")                                                            \
        for (int jj = 0; jj < 4; jj++) {                                             \
            const int k = b_k + jj * 8;                                              \
            cp_async16(sb + k * (LDBW * 4) + b_chk * 16,                             \
                       gB + (size_t)((it) * 32 + k) * JDIM + b_chk * 4);             \
        }                                                                            \
    } while (0)

    MAIN_LOAD(0, 0); CP_COMMIT();
    MAIN_LOAD(1, 1); CP_COMMIT();

    int slot_c = 0;
    for (int it = 0; it < GEMM_ITERS; ++it) {
        CP_WAIT1();
        __syncthreads();
        if (it + 2 < GEMM_ITERS) MAIN_LOAD(it + 2, (it + 2) % 3);
        CP_COMMIT();

        const uint32_t* As = smu + slot_c * (STAGE_BYTES / 4);
        const uint32_t* Bs = As + (A_STAGE_BYTES / 4);
        const int arow_base = wm * 64 + qrow;
        const int bcol_base = wn * 64 + qrow;
#pragma unroll
        for (int ks = 0; ks < 4; ks++) {
            const int kw = ks * 8 + qcol;   // uint32 (bf16-pair) index within BK
            uint32_t af[4][4];
#pragma unroll
            for (int mt = 0; mt < 4; mt++) {
                const uint32_t* ap = As + (arow_base + mt * 16) * LDAW + kw;
                af[mt][0] = ap[0];
                af[mt][1] = ap[8 * LDAW];
                af[mt][2] = ap[4];
                af[mt][3] = ap[8 * LDAW + 4];
            }
            uint32_t bf[8][2];
#pragma unroll
            for (int nt = 0; nt < 8; nt++) {
                const uint32_t* bp = Bs + kw * LDBW + bcol_base + nt * 8;
                bf[nt][0] = bp[0];
                bf[nt][1] = bp[4 * LDBW];
            }
#pragma unroll
            for (int mt = 0; mt < 4; mt++)
#pragma unroll
                for (int nt = 0; nt < 8; nt++)
                    mma_bf16(acc[mt][nt], af[mt], bf[nt]);
        }
        slot_c = (slot_c + 1) % 3;
    }
#undef MAIN_LOAD

    // ---- epilogue: + U0 + bias, scatter to out[bz][n][t] ----
    const int j0 = col0 + wn * 64;
    const int bz = j0 >> 6;
    const float bv = bias[bz & 31];
#pragma unroll
    for (int mt = 0; mt < 4; mt++) {
#pragma unroll
        for (int h = 0; h < 2; h++) {
            const int n = row0 + wm * 64 + mt * 16 + h * 8 + qrow;
            float* orow = out + (size_t)bz * (NN * TT) + (size_t)n * TT;
            const float* u0row = U0 + (size_t)n * JDIM + j0;
#pragma unroll
            for (int nt = 0; nt < 8; nt++) {
                const int t = nt * 8 + qcol * 2;
                const float2 u = *reinterpret_cast<const float2*>(u0row + t);
                float2 v;
                v.x = acc[mt][nt][h * 2 + 0] + u.x + bv;
                v.y = acc[mt][nt][h * 2 + 1] + u.y + bv;
                *reinterpret_cast<float2*>(orow + t) = v;
            }
        }
    }
}

// ---------------------------------------------------------------------------
// Launch
// ---------------------------------------------------------------------------
extern "C" void kernel_launch(void* const* d_in, const int* in_sizes, int n_in,
                              void* d_out, int out_size)
{
    const float* x  = (const float*)d_in[0];
    const float* AL = (const float*)d_in[1];
    const float* AS = (const float*)d_in[2];
    const float* W  = (const float*)d_in[3];
    const float* bm = (const float*)d_in[4];
    float* out = (float*)d_out;

    uint32_t *pUw2, *pM2;
    float *pU0, *pALr, *pASr, *pG1, *pG2, *pS, *pG1p;
    cudaGetSymbolAddress((void**)&pUw2, g_Uw2);
    cudaGetSymbolAddress((void**)&pU0,  g_U0);
    cudaGetSymbolAddress((void**)&pM2,  g_M2);
    cudaGetSymbolAddress((void**)&pALr, g_ALr);
    cudaGetSymbolAddress((void**)&pASr, g_ASr);
    cudaGetSymbolAddress((void**)&pG1,  g_G1);
    cudaGetSymbolAddress((void**)&pG2,  g_G2);
    cudaGetSymbolAddress((void**)&pS,   g_S);
    cudaGetSymbolAddress((void**)&pG1p, g_G1p);

    cudaFuncSetAttribute(gemm_pre_tf32,
                         cudaFuncAttributeMaxDynamicSharedMemorySize, SMEM_GEMM);
    cudaFuncSetAttribute(main_gemm_bf16,
                         cudaFuncAttributeMaxDynamicSharedMemorySize, SMEM_GEMM);

    // 0) tf32-round the adjacency inputs
    ew_tf32copy<<<4096, 256>>>(AL, pALr);
    ew_tf32copy<<<4096, 256>>>(AS, pASr);

    // 1) stage-1 GEMMs: G1 = AL^2 , G2 = AS*AL  (tf32-rounded outputs)
    const dim3 gpre(1024 / BM, 1024 / BN, 2);   // 4 x 8 x 2
    gemm_pre_tf32<<<gpre, 256, SMEM_GEMM>>>(pALr, pASr, pALr, pALr, pG1, pG2, 1);

    // 2) S = tf32(AS - AS*AL)
    ew_axpby_r<<<4096, 256>>>(pASr, pG2, pS, -1.0f);

    // 3) stage-2 GEMMs: G2p = AL*G1 (=AL^3) , G1p = AS*S (=AS^2(I-AL))
    gemm_pre_tf32<<<gpre, 256, SMEM_GEMM>>>(pALr, pASr, pG1, pS, pG2, pG1p, 0);

    // 4) M (bf16x2 interleaved): lo = G1+S (=M1), hi = G2p+G1p (=M2)
    ew_buildM<<<4096, 256>>>(pG1, pS, pG2, pG1p, pM2);

    // 5) channel mix: U0 fp32, (u1,u2) packed bf16x2
    chanmix_kernel<<<dim3(NN / 4, BB), 256>>>(x, W, pUw2, pU0);

    // 6) main bf16 tensor GEMM + fused epilogue (row tiles fast => B reuse in L2)
    main_gemm_bf16<<<dim3(NN / BM, JDIM / BN), 256, SMEM_GEMM>>>(pM2, pUw2, pU0, bm, out);
}

// round 10
// speedup vs baseline: 4.7309x; 1.0065x over previous
#include <cuda_runtime.h>
#include <cuda_bf16.h>
#include <cstdint>

// ---------------------------------------------------------------------------
// Problem constants
// ---------------------------------------------------------------------------
#define NN   1024
#define TT   64
#define BB   16
#define JDIM 32768         // B*C_OUT*T = 512*64

// GEMM tiling: CTA 256x128, 256 thr, 8 warps (4M x 2N)
#define BM 256
#define BN 128
#define LDAW 36                          // uint32 per A smem row (32 data + 4 pad)
#define LDBW 136                         // uint32 per B smem row (128 data + 8 pad)
#define A_STAGE_BYTES (BM * LDAW * 4)    // 36864
#define B_STAGE_BYTES (32 * LDBW * 4)    // 17408
#define STAGE_BYTES (A_STAGE_BYTES + B_STAGE_BYTES)   // 54272
#define SMEM_PRE  (3 * STAGE_BYTES)      // 162816
#define SMEM_MAIN (4 * STAGE_BYTES)      // 217088
#define GEMM_ITERS 32    // pre: K=1024/BK32 ; main: K=2048 bf16 / BK64

// ---------------------------------------------------------------------------
// Scratch (device globals; allocations are forbidden)
// ---------------------------------------------------------------------------
__device__ __align__(128) uint32_t g_Uw2[(size_t)NN * JDIM]; // [m][j] bf16x2 (u1,u2) 128MB
__device__ __align__(128) float    g_U0 [(size_t)NN * JDIM]; // [n][j] fp32           128MB
__device__ __align__(128) uint32_t g_M2 [NN * NN];           // [n][m] bf16x2 (M1,M2) 4MB
__device__ __align__(128) float g_G1 [NN * NN];   // AL^2
__device__ __align__(128) float g_S  [NN * NN];   // AS(I-AL)
__device__ __align__(128) float g_G2p[NN * NN];   // AL^3
__device__ __align__(128) float g_G1p[NN * NN];   // AS^2(I-AL)

// ---------------------------------------------------------------------------
// Helpers
// ---------------------------------------------------------------------------
__device__ __forceinline__ uint32_t smem_u32(const void* p) {
    uint32_t a;
    asm("{ .reg .u64 t; cvta.to.shared.u64 t, %1; cvt.u32.u64 %0, t; }" : "=r"(a) : "l"(p));
    return a;
}
__device__ __forceinline__ void cp_async16(uint32_t saddr, const void* gaddr) {
    asm volatile("cp.async.cg.shared.global [%0], [%1], 16;" :: "r"(saddr), "l"(gaddr) : "memory");
}
#define CP_COMMIT() asm volatile("cp.async.commit_group;" ::: "memory")
#define CP_WAIT1()  asm volatile("cp.async.wait_group 1;" ::: "memory")
#define CP_WAIT2()  asm volatile("cp.async.wait_group 2;" ::: "memory")

__device__ __forceinline__ void mma_tf32(float* d, const uint32_t* a, const uint32_t* b) {
    asm volatile(
        "mma.sync.aligned.m16n8k8.row.col.f32.tf32.tf32.f32 "
        "{%0,%1,%2,%3}, {%4,%5,%6,%7}, {%8,%9}, {%0,%1,%2,%3};\n"
        : "+f"(d[0]), "+f"(d[1]), "+f"(d[2]), "+f"(d[3])
        : "r"(a[0]), "r"(a[1]), "r"(a[2]), "r"(a[3]), "r"(b[0]), "r"(b[1]));
}
__device__ __forceinline__ void mma_bf16(float* d, const uint32_t* a, const uint32_t* b) {
    asm volatile(
        "mma.sync.aligned.m16n8k16.row.col.f32.bf16.bf16.f32 "
        "{%0,%1,%2,%3}, {%4,%5,%6,%7}, {%8,%9}, {%0,%1,%2,%3};\n"
        : "+f"(d[0]), "+f"(d[1]), "+f"(d[2]), "+f"(d[3])
        : "r"(a[0]), "r"(a[1]), "r"(a[2]), "r"(a[3]), "r"(b[0]), "r"(b[1]));
}
__device__ __forceinline__ void ldsm_x4(uint32_t* r, uint32_t saddr) {
    asm volatile("ldmatrix.sync.aligned.m8n8.x4.shared.b16 {%0,%1,%2,%3}, [%4];"
                 : "=r"(r[0]), "=r"(r[1]), "=r"(r[2]), "=r"(r[3]) : "r"(saddr));
}

// ---------------------------------------------------------------------------
// M2d[idx] = bf16x2( X1+Y1 , X2+Y2 )   (lo = M1, hi = M2)
// ---------------------------------------------------------------------------
__global__ __launch_bounds__(256) void ew_buildM(
    const float* __restrict__ X1, const float* __restrict__ Y1,
    const float* __restrict__ X2, const float* __restrict__ Y2,
    uint32_t* __restrict__ M2d)
{
    int idx = blockIdx.x * 256 + threadIdx.x;
    __nv_bfloat162 v = __floats2bfloat162_rn(X1[idx] + Y1[idx], X2[idx] + Y2[idx]);
    M2d[idx] = *reinterpret_cast<uint32_t*>(&v);
}

// ---------------------------------------------------------------------------
// Precompute GEMM (tf32 mma, fp32 in/out; mma truncates operands to tf32):
//   z=0: C0 = A0 @ B0            z=1: C1 = A1 @ B1, or sub - A1@B1 if sub != 0
// ---------------------------------------------------------------------------
__global__ __launch_bounds__(256, 1) void gemm_pre_tf32(
    const float* __restrict__ A0, const float* __restrict__ A1,
    const float* __restrict__ B0, const float* __restrict__ B1,
    float* __restrict__ C0, float* __restrict__ C1,
    const float* __restrict__ sub)
{
    extern __shared__ __align__(1024) char smem[];
    const uint32_t sbase = smem_u32(smem);
    float* smf = reinterpret_cast<float*>(smem);

    const int tid  = threadIdx.x;
    const int wid  = tid >> 5;
    const int lane = tid & 31;
    const int wm   = wid >> 1;
    const int wn   = wid & 1;
    const int qrow = lane >> 2;
    const int qcol = lane & 3;

    const int row0 = blockIdx.x * BM;
    const int col0 = blockIdx.y * BN;
    const float* gA = (blockIdx.z ? A1 : A0) + (size_t)row0 * 1024;
    const float* gB = (blockIdx.z ? B1 : B0) + col0;
    float* gC = (blockIdx.z ? C1 : C0);
    const float* gSub = (blockIdx.z && sub) ? sub : nullptr;

    float acc[4][8][4];
#pragma unroll
    for (int mt = 0; mt < 4; mt++)
#pragma unroll
        for (int nt = 0; nt < 8; nt++)
#pragma unroll
            for (int q = 0; q < 4; q++) acc[mt][nt][q] = 0.0f;

    const int a_row = tid >> 3;
    const int a_chk = tid & 7;
    const int b_k   = tid >> 5;
    const int b_chk = tid & 31;

#define PRE_LOAD(it, slot)                                                           \
    do {                                                                             \
        const uint32_t sa = sbase + (slot) * STAGE_BYTES;                            \
        const uint32_t sb = sa + A_STAGE_BYTES;                                      \
        const int koff = (it) * 32;                                                  \
        _Pragma("unroll")                                                            \
        for (int jj = 0; jj < 8; jj++) {                                             \
            const int r = a_row + jj * 32;                                           \
            cp_async16(sa + r * (LDAW * 4) + a_chk * 16,                             \
                       gA + (size_t)r * 1024 + koff + a_chk * 4);                    \
        }                                                                            \
        _Pragma("unroll")                                                            \
        for (int jj = 0; jj < 4; jj++) {                                             \
            const int k = b_k + jj * 8;                                              \
            cp_async16(sb + k * (LDBW * 4) + b_chk * 16,                             \
                       gB + (size_t)(koff + k) * 1024 + b_chk * 4);                  \
        }                                                                            \
    } while (0)

    PRE_LOAD(0, 0); CP_COMMIT();
    PRE_LOAD(1, 1); CP_COMMIT();

    int slot_c = 0;
    for (int it = 0; it < GEMM_ITERS; ++it) {
        CP_WAIT1();
        __syncthreads();
        if (it + 2 < GEMM_ITERS) PRE_LOAD(it + 2, (it + 2) % 3);
        CP_COMMIT();

        const float* As = smf + slot_c * (STAGE_BYTES / 4);
        const float* Bs = As + (A_STAGE_BYTES / 4);
        const int arow_base = wm * 64 + qrow;
        const int bcol_base = wn * 64 + qrow;
#pragma unroll
        for (int ks = 0; ks < 4; ks++) {
            const int k0 = ks * 8;
            uint32_t af[4][4];
#pragma unroll
            for (int mt = 0; mt < 4; mt++) {
                const float* ap = As + (arow_base + mt * 16) * LDAW + k0 + qcol;
                af[mt][0] = __float_as_uint(ap[0]);
                af[mt][1] = __float_as_uint(ap[8 * LDAW]);
                af[mt][2] = __float_as_uint(ap[4]);
                af[mt][3] = __float_as_uint(ap[8 * LDAW + 4]);
            }
            uint32_t bf[8][2];
#pragma unroll
            for (int nt = 0; nt < 8; nt++) {
                const float* bp = Bs + (k0 + qcol) * LDBW + bcol_base + nt * 8;
                bf[nt][0] = __float_as_uint(bp[0]);
                bf[nt][1] = __float_as_uint(bp[4 * LDBW]);
            }
#pragma unroll
            for (int mt = 0; mt < 4; mt++)
#pragma unroll
                for (int nt = 0; nt < 8; nt++)
                    mma_tf32(acc[mt][nt], af[mt], bf[nt]);
        }
        slot_c = (slot_c + 1) % 3;
    }
#undef PRE_LOAD

#pragma unroll
    for (int mt = 0; mt < 4; mt++) {
#pragma unroll
        for (int h = 0; h < 2; h++) {
            const int n = row0 + wm * 64 + mt * 16 + h * 8 + qrow;
            const size_t base = (size_t)n * 1024 + col0 + wn * 64;
#pragma unroll
            for (int nt = 0; nt < 8; nt++) {
                float vx = acc[mt][nt][h * 2 + 0];
                float vy = acc[mt][nt][h * 2 + 1];
                const size_t off = base + nt * 8 + qcol * 2;
                if (gSub) {
                    const float2 s = *reinterpret_cast<const float2*>(gSub + off);
                    vx = s.x - vx; vy = s.y - vy;
                }
                *reinterpret_cast<float2*>(gC + off) = make_float2(vx, vy);
            }
        }
    }
}

// ---------------------------------------------------------------------------
// Channel mix: u_g[o] = sum_c W[o*96+32g+c] * x[b,c,n,t]
//   g=0 -> U0[n][j] fp32;  (g=1,g=2) -> Uw2[n][j] packed bf16x2 (lo=u1, hi=u2)
//   j = (b*32+o)*64 + t
// ---------------------------------------------------------------------------
__global__ __launch_bounds__(256) void chanmix_kernel(
    const float* __restrict__ x, const float* __restrict__ W,
    uint32_t* __restrict__ Uw2, float* __restrict__ U0)
{
    __shared__ float Ws[32 * 96];
    const int tid = threadIdx.x;
#pragma unroll
    for (int i = 0; i < 12; i++) Ws[tid + i * 256] = W[tid + i * 256];
    __syncthreads();

    const int t  = tid & 63;
    const int nn = tid >> 6;
    const int n  = blockIdx.x * 4 + nn;
    const int b  = blockIdx.y;

    float xv[32];
    const size_t xbase = (((size_t)b * 32) * NN + n) * TT + t;
#pragma unroll
    for (int c = 0; c < 32; c++)
        xv[c] = x[xbase + (size_t)c * NN * TT];

    for (int o = 0; o < 32; o++) {
        float a0 = 0.f, a1 = 0.f, a2 = 0.f;
        const float* wr = &Ws[o * 96];
#pragma unroll
        for (int c = 0; c < 32; c++) {
            const float xc = xv[c];
            a0 += wr[c]      * xc;
            a1 += wr[32 + c] * xc;
            a2 += wr[64 + c] * xc;
        }
        const size_t j = ((size_t)(b * 32 + o)) * 64 + t;
        U0[(size_t)n * JDIM + j] = a0;
        __nv_bfloat162 p = __floats2bfloat162_rn(a1, a2);
        Uw2[(size_t)n * JDIM + j] = *reinterpret_cast<uint32_t*>(&p);
    }
}

// ---------------------------------------------------------------------------
// Main GEMM (bf16 mma m16n8k16, ldmatrix A frags, 4-stage cp.async):
//   D[1024 x 32768] = Mb[1024 x 2048 bf16] @ U  (U packed bf16x2 pair rows)
//   out[bz][n][t] = D[n][j] + U0[n][j] + bias[bz & 31]
// ---------------------------------------------------------------------------
__global__ __launch_bounds__(256, 1) void main_gemm_bf16(
    const uint32_t* __restrict__ Mb2, const uint32_t* __restrict__ Uw2,
    const float* __restrict__ U0,     const float* __restrict__ bias,
    float* __restrict__ out)
{
    extern __shared__ __align__(1024) char smem[];
    const uint32_t sbase = smem_u32(smem);
    const uint32_t* smu = reinterpret_cast<uint32_t*>(smem);

    const int tid  = threadIdx.x;
    const int wid  = tid >> 5;
    const int lane = tid & 31;
    const int wm   = wid >> 1;
    const int wn   = wid & 1;
    const int qrow = lane >> 2;
    const int qcol = lane & 3;
    const int lrow = lane & 15;              // ldmatrix row within 16-row tile
    const int lkw  = (lane >> 4) << 2;       // ldmatrix kw offset (0 or 4)

    const int row0 = blockIdx.x * BM;
    const int col0 = blockIdx.y * BN;

    float acc[4][8][4];
#pragma unroll
    for (int mt = 0; mt < 4; mt++)
#pragma unroll
        for (int nt = 0; nt < 8; nt++)
#pragma unroll
            for (int q = 0; q < 4; q++) acc[mt][nt][q] = 0.0f;

    const int a_row = tid >> 3;
    const int a_chk = tid & 7;    // 8 x 16B = 128B = 64 bf16 (BK)
    const int b_k   = tid >> 5;
    const int b_chk = tid & 31;   // 32 x 16B = 512B = 128 uint32 (BN)

    const char* gA = (const char*)Mb2 + (size_t)row0 * (NN * 4);
    const uint32_t* gB = Uw2 + col0;

#define MAIN_LOAD(it, slot)                                                          \
    do {                                                                             \
        const uint32_t sa = sbase + (slot) * STAGE_BYTES;                            \
        const uint32_t sb = sa + A_STAGE_BYTES;                                      \
        _Pragma("unroll")                                                            \
        for (int jj = 0; jj < 8; jj++) {                                             \
            const int r = a_row + jj * 32;                                           \
            cp_async16(sa + r * (LDAW * 4) + a_chk * 16,                             \
                       gA + (size_t)r * (NN * 4) + (it) * 128 + a_chk * 16);         \
        }                                                                            \
        _Pragma("unroll")                                                            \
        for (int jj = 0; jj < 4; jj++) {                                             \
            const int k = b_k + jj * 8;                                              \
            cp_async16(sb + k * (LDBW * 4) + b_chk * 16,                             \
                       gB + (size_t)((it) * 32 + k) * JDIM + b_chk * 4);             \
        }                                                                            \
    } while (0)

    MAIN_LOAD(0, 0); CP_COMMIT();
    MAIN_LOAD(1, 1); CP_COMMIT();
    MAIN_LOAD(2, 2); CP_COMMIT();

    int slot_c = 0;
    for (int it = 0; it < GEMM_ITERS; ++it) {
        CP_WAIT2();
        __syncthreads();
        if (it + 3 < GEMM_ITERS) MAIN_LOAD(it + 3, (it + 3) & 3);
        CP_COMMIT();

        const uint32_t As_b = sbase + slot_c * STAGE_BYTES;
        const uint32_t* Bs = smu + slot_c * (STAGE_BYTES / 4) + (A_STAGE_BYTES / 4);
        const int bcol_base = wn * 64 + qrow;
#pragma unroll
        for (int ks = 0; ks < 4; ks++) {
            const int kw = ks * 8 + qcol;
            uint32_t af[4][4];
#pragma unroll
            for (int mt = 0; mt < 4; mt++) {
                const uint32_t addr = As_b +
                    (uint32_t)(((wm * 64 + mt * 16 + lrow) * LDAW) + ks * 8 + lkw) * 4;
                ldsm_x4(af[mt], addr);
            }
            uint32_t bf[8][2];
#pragma unroll
            for (int nt = 0; nt < 8; nt++) {
                const uint32_t* bp = Bs + kw * LDBW + bcol_base + nt * 8;
                bf[nt][0] = bp[0];
                bf[nt][1] = bp[4 * LDBW];
            }
#pragma unroll
            for (int mt = 0; mt < 4; mt++)
#pragma unroll
                for (int nt = 0; nt < 8; nt++)
                    mma_bf16(acc[mt][nt], af[mt], bf[nt]);
        }
        slot_c = (slot_c + 1) & 3;
    }
#undef MAIN_LOAD

    // ---- epilogue: + U0 + bias, scatter to out[bz][n][t] ----
    const int j0 = col0 + wn * 64;
    const int bz = j0 >> 6;
    const float bv = bias[bz & 31];
#pragma unroll
    for (int mt = 0; mt < 4; mt++) {
#pragma unroll
        for (int h = 0; h < 2; h++) {
            const int n = row0 + wm * 64 + mt * 16 + h * 8 + qrow;
            float* orow = out + (size_t)bz * (NN * TT) + (size_t)n * TT;
            const float* u0row = U0 + (size_t)n * JDIM + j0;
#pragma unroll
            for (int nt = 0; nt < 8; nt++) {
                const int t = nt * 8 + qcol * 2;
                const float2 u = *reinterpret_cast<const float2*>(u0row + t);
                float2 v;
                v.x = acc[mt][nt][h * 2 + 0] + u.x + bv;
                v.y = acc[mt][nt][h * 2 + 1] + u.y + bv;
                *reinterpret_cast<float2*>(orow + t) = v;
            }
        }
    }
}

// ---------------------------------------------------------------------------
// Launch
// ---------------------------------------------------------------------------
extern "C" void kernel_launch(void* const* d_in, const int* in_sizes, int n_in,
                              void* d_out, int out_size)
{
    const float* x  = (const float*)d_in[0];
    const float* AL = (const float*)d_in[1];
    const float* AS = (const float*)d_in[2];
    const float* W  = (const float*)d_in[3];
    const float* bm = (const float*)d_in[4];
    float* out = (float*)d_out;

    uint32_t *pUw2, *pM2;
    float *pU0, *pG1, *pS, *pG2p, *pG1p;
    cudaGetSymbolAddress((void**)&pUw2, g_Uw2);
    cudaGetSymbolAddress((void**)&pU0,  g_U0);
    cudaGetSymbolAddress((void**)&pM2,  g_M2);
    cudaGetSymbolAddress((void**)&pG1,  g_G1);
    cudaGetSymbolAddress((void**)&pS,   g_S);
    cudaGetSymbolAddress((void**)&pG2p, g_G2p);
    cudaGetSymbolAddress((void**)&pG1p, g_G1p);

    cudaFuncSetAttribute(gemm_pre_tf32,
                         cudaFuncAttributeMaxDynamicSharedMemorySize, SMEM_PRE);
    cudaFuncSetAttribute(main_gemm_bf16,
                         cudaFuncAttributeMaxDynamicSharedMemorySize, SMEM_MAIN);

    const dim3 gpre(1024 / BM, 1024 / BN, 2);   // 4 x 8 x 2

    // stage 1: G1 = AL^2 ; S = AS - AS*AL  (subtract fused into z=1 epilogue)
    gemm_pre_tf32<<<gpre, 256, SMEM_PRE>>>(AL, AS, AL, AL, pG1, pS, AS);

    // stage 2: G2p = AL*G1 (=AL^3) ; G1p = AS*S (=AS^2(I-AL))
    gemm_pre_tf32<<<gpre, 256, SMEM_PRE>>>(AL, AS, pG1, pS, pG2p, pG1p, nullptr);

    // M (bf16x2 interleaved): lo = G1+S (=M1), hi = G2p+G1p (=M2)
    ew_buildM<<<4096, 256>>>(pG1, pS, pG2p, pG1p, pM2);

    // channel mix: U0 fp32, (u1,u2) packed bf16x2
    chanmix_kernel<<<dim3(NN / 4, BB), 256>>>(x, W, pUw2, pU0);

    // main bf16 tensor GEMM + fused epilogue (row tiles fast => B reuse in L2)
    main_gemm_bf16<<<dim3(NN / BM, JDIM / BN), 256, SMEM_MAIN>>>(pM2, pUw2, pU0, bm, out);
}

// round 11
// speedup vs baseline: 4.9955x; 1.0559x over previous
#include <cuda_runtime.h>
#include <cuda_bf16.h>
#include <cstdint>

// ---------------------------------------------------------------------------
// Problem constants
// ---------------------------------------------------------------------------
#define NN   1024
#define TT   64
#define BB   16
#define JDIM 32768         // B*C_OUT*T = 512*64

// main GEMM tiling: CTA 256x128, 256 thr, 8 warps (4M x 2N)
#define BM 256
#define BN 128
#define LDAW 36                          // uint32 per A smem row (32 data + 4 pad)
#define LDBW 136                         // uint32 per B smem row (128 data + 8 pad)
#define A_STAGE_BYTES (BM * LDAW * 4)    // 36864
#define B_STAGE_BYTES (32 * LDBW * 4)    // 17408
#define STAGE_BYTES (A_STAGE_BYTES + B_STAGE_BYTES)   // 54272
#define SMEM_MAIN (4 * STAGE_BYTES)      // 217088
#define GEMM_ITERS 32    // pre: K=1024/BK32 ; main: K=2048 bf16 / BK64

// precompute GEMM tiling: CTA 256x64 (grid 4x16x2 = 128 CTAs, fills the chip)
#define PRE_BN 64
#define PRE_LDBW 72                      // 64 data + 8 pad
#define PRE_B_STAGE (32 * PRE_LDBW * 4)  // 9216
#define PRE_STAGE_BYTES (A_STAGE_BYTES + PRE_B_STAGE)  // 46080
#define SMEM_PRE (3 * PRE_STAGE_BYTES)                  // 138240

// ---------------------------------------------------------------------------
// Scratch (device globals; allocations are forbidden)
// ---------------------------------------------------------------------------
__device__ __align__(128) uint32_t g_Uw2[(size_t)NN * JDIM]; // [m][j] bf16x2 (u1,u2) 128MB
__device__ __align__(128) float    g_U0 [(size_t)NN * JDIM]; // [n][j] fp32           128MB
__device__ __align__(128) uint32_t g_M2 [NN * NN];           // [n][m] bf16x2 (M1,M2) 4MB
__device__ __align__(128) float g_G1 [NN * NN];   // AL^2
__device__ __align__(128) float g_S  [NN * NN];   // AS(I-AL)
__device__ __align__(128) float g_G2p[NN * NN];   // AL^3
__device__ __align__(128) float g_G1p[NN * NN];   // AS^2(I-AL)

// ---------------------------------------------------------------------------
// Helpers
// ---------------------------------------------------------------------------
__device__ __forceinline__ uint32_t smem_u32(const void* p) {
    uint32_t a;
    asm("{ .reg .u64 t; cvta.to.shared.u64 t, %1; cvt.u32.u64 %0, t; }" : "=r"(a) : "l"(p));
    return a;
}
__device__ __forceinline__ void cp_async16(uint32_t saddr, const void* gaddr) {
    asm volatile("cp.async.cg.shared.global [%0], [%1], 16;" :: "r"(saddr), "l"(gaddr) : "memory");
}
#define CP_COMMIT() asm volatile("cp.async.commit_group;" ::: "memory")
#define CP_WAIT1()  asm volatile("cp.async.wait_group 1;" ::: "memory")
#define CP_WAIT2()  asm volatile("cp.async.wait_group 2;" ::: "memory")

__device__ __forceinline__ void mma_tf32(float* d, const uint32_t* a, const uint32_t* b) {
    asm volatile(
        "mma.sync.aligned.m16n8k8.row.col.f32.tf32.tf32.f32 "
        "{%0,%1,%2,%3}, {%4,%5,%6,%7}, {%8,%9}, {%0,%1,%2,%3};\n"
        : "+f"(d[0]), "+f"(d[1]), "+f"(d[2]), "+f"(d[3])
        : "r"(a[0]), "r"(a[1]), "r"(a[2]), "r"(a[3]), "r"(b[0]), "r"(b[1]));
}
__device__ __forceinline__ void mma_bf16(float* d, const uint32_t* a, const uint32_t* b) {
    asm volatile(
        "mma.sync.aligned.m16n8k16.row.col.f32.bf16.bf16.f32 "
        "{%0,%1,%2,%3}, {%4,%5,%6,%7}, {%8,%9}, {%0,%1,%2,%3};\n"
        : "+f"(d[0]), "+f"(d[1]), "+f"(d[2]), "+f"(d[3])
        : "r"(a[0]), "r"(a[1]), "r"(a[2]), "r"(a[3]), "r"(b[0]), "r"(b[1]));
}
__device__ __forceinline__ void ldsm_x4(uint32_t* r, uint32_t saddr) {
    asm volatile("ldmatrix.sync.aligned.m8n8.x4.shared.b16 {%0,%1,%2,%3}, [%4];"
                 : "=r"(r[0]), "=r"(r[1]), "=r"(r[2]), "=r"(r[3]) : "r"(saddr));
}

// ---------------------------------------------------------------------------
// M2d[idx] = bf16x2( X1+Y1 , X2+Y2 )   (lo = M1, hi = M2)
// ---------------------------------------------------------------------------
__global__ __launch_bounds__(256) void ew_buildM(
    const float* __restrict__ X1, const float* __restrict__ Y1,
    const float* __restrict__ X2, const float* __restrict__ Y2,
    uint32_t* __restrict__ M2d)
{
    int idx = blockIdx.x * 256 + threadIdx.x;
    __nv_bfloat162 v = __floats2bfloat162_rn(X1[idx] + Y1[idx], X2[idx] + Y2[idx]);
    M2d[idx] = *reinterpret_cast<uint32_t*>(&v);
}

// ---------------------------------------------------------------------------
// Precompute GEMM (tf32 mma, fp32 in/out; mma truncates operands to tf32):
//   z=0: C0 = A0 @ B0      z=1: C1 = A1 @ B1, or sub - A1@B1 if sub != 0
// CTA 256x64, 8 warps = 4M x 2N, warp tile 64x32.
// ---------------------------------------------------------------------------
__global__ __launch_bounds__(256, 1) void gemm_pre_tf32(
    const float* __restrict__ A0, const float* __restrict__ A1,
    const float* __restrict__ B0, const float* __restrict__ B1,
    float* __restrict__ C0, float* __restrict__ C1,
    const float* __restrict__ sub)
{
    extern __shared__ __align__(1024) char smem[];
    const uint32_t sbase = smem_u32(smem);
    float* smf = reinterpret_cast<float*>(smem);

    const int tid  = threadIdx.x;
    const int wid  = tid >> 5;
    const int lane = tid & 31;
    const int wm   = wid >> 1;      // 0..3 (64 rows each)
    const int wn   = wid & 1;       // 0..1 (32 cols each)
    const int qrow = lane >> 2;
    const int qcol = lane & 3;

    const int row0 = blockIdx.x * BM;
    const int col0 = blockIdx.y * PRE_BN;
    const float* gA = (blockIdx.z ? A1 : A0) + (size_t)row0 * 1024;
    const float* gB = (blockIdx.z ? B1 : B0) + col0;
    float* gC = (blockIdx.z ? C1 : C0);
    const float* gSub = (blockIdx.z && sub) ? sub : nullptr;

    float acc[4][4][4];
#pragma unroll
    for (int mt = 0; mt < 4; mt++)
#pragma unroll
        for (int nt = 0; nt < 4; nt++)
#pragma unroll
            for (int q = 0; q < 4; q++) acc[mt][nt][q] = 0.0f;

    const int a_row = tid >> 3;
    const int a_chk = tid & 7;    // 8 x 16B = 32 floats (BK)
    const int b_k   = tid >> 4;   // 0..15
    const int b_chk = tid & 15;   // 16 x 16B = 64 floats (PRE_BN)

#define PRE_LOAD(it, slot)                                                           \
    do {                                                                             \
        const uint32_t sa = sbase + (slot) * PRE_STAGE_BYTES;                        \
        const uint32_t sb = sa + A_STAGE_BYTES;                                      \
        const int koff = (it) * 32;                                                  \
        _Pragma("unroll")                                                            \
        for (int jj = 0; jj < 8; jj++) {                                             \
            const int r = a_row + jj * 32;                                           \
            cp_async16(sa + r * (LDAW * 4) + a_chk * 16,                             \
                       gA + (size_t)r * 1024 + koff + a_chk * 4);                    \
        }                                                                            \
        _Pragma("unroll")                                                            \
        for (int jj = 0; jj < 2; jj++) {                                             \
            const int k = b_k + jj * 16;                                             \
            cp_async16(sb + k * (PRE_LDBW * 4) + b_chk * 16,                         \
                       gB + (size_t)(koff + k) * 1024 + b_chk * 4);                  \
        }                                                                            \
    } while (0)

    PRE_LOAD(0, 0); CP_COMMIT();
    PRE_LOAD(1, 1); CP_COMMIT();

    int slot_c = 0;
    for (int it = 0; it < GEMM_ITERS; ++it) {
        CP_WAIT1();
        __syncthreads();
        if (it + 2 < GEMM_ITERS) PRE_LOAD(it + 2, (it + 2) % 3);
        CP_COMMIT();

        const float* As = smf + slot_c * (PRE_STAGE_BYTES / 4);
        const float* Bs = As + (A_STAGE_BYTES / 4);
        const int arow_base = wm * 64 + qrow;
        const int bcol_base = wn * 32 + qrow;
#pragma unroll
        for (int ks = 0; ks < 4; ks++) {
            const int k0 = ks * 8;
            uint32_t af[4][4];
#pragma unroll
            for (int mt = 0; mt < 4; mt++) {
                const float* ap = As + (arow_base + mt * 16) * LDAW + k0 + qcol;
                af[mt][0] = __float_as_uint(ap[0]);
                af[mt][1] = __float_as_uint(ap[8 * LDAW]);
                af[mt][2] = __float_as_uint(ap[4]);
                af[mt][3] = __float_as_uint(ap[8 * LDAW + 4]);
            }
            uint32_t bf[4][2];
#pragma unroll
            for (int nt = 0; nt < 4; nt++) {
                const float* bp = Bs + (k0 + qcol) * PRE_LDBW + bcol_base + nt * 8;
                bf[nt][0] = __float_as_uint(bp[0]);
                bf[nt][1] = __float_as_uint(bp[4 * PRE_LDBW]);
            }
#pragma unroll
            for (int mt = 0; mt < 4; mt++)
#pragma unroll
                for (int nt = 0; nt < 4; nt++)
                    mma_tf32(acc[mt][nt], af[mt], bf[nt]);
        }
        slot_c = (slot_c + 1) % 3;
    }
#undef PRE_LOAD

#pragma unroll
    for (int mt = 0; mt < 4; mt++) {
#pragma unroll
        for (int h = 0; h < 2; h++) {
            const int n = row0 + wm * 64 + mt * 16 + h * 8 + qrow;
            const size_t base = (size_t)n * 1024 + col0 + wn * 32;
#pragma unroll
            for (int nt = 0; nt < 4; nt++) {
                float vx = acc[mt][nt][h * 2 + 0];
                float vy = acc[mt][nt][h * 2 + 1];
                const size_t off = base + nt * 8 + qcol * 2;
                if (gSub) {
                    const float2 s = *reinterpret_cast<const float2*>(gSub + off);
                    vx = s.x - vx; vy = s.y - vy;
                }
                *reinterpret_cast<float2*>(gC + off) = make_float2(vx, vy);
            }
        }
    }
}

// ---------------------------------------------------------------------------
// Channel mix: u_g[o] = sum_c W[o*96+32g+c] * x[b,c,n,t]
//   g=0 -> U0[n][j] fp32;  (g=1,g=2) -> Uw2[n][j] packed bf16x2 (lo=u1, hi=u2)
//   j = (b*32+o)*64 + t
// W read via float4 broadcast LDS (24 LDS.128 per o instead of 96 LDS.32);
// 4 independent accumulator chains per output to expose FMA ILP.
// ---------------------------------------------------------------------------
__global__ __launch_bounds__(256) void chanmix_kernel(
    const float* __restrict__ x, const float* __restrict__ W,
    uint32_t* __restrict__ Uw2, float* __restrict__ U0)
{
    __shared__ float4 Ws4[768];    // 32 rows x 24 float4 (= 96 floats per row)
    const int tid = threadIdx.x;
    {
        const float4* Wg = reinterpret_cast<const float4*>(W);
#pragma unroll
        for (int i = 0; i < 3; i++) Ws4[tid + i * 256] = Wg[tid + i * 256];
    }
    __syncthreads();

    const int t  = tid & 63;
    const int nn = tid >> 6;
    const int n  = blockIdx.x * 4 + nn;
    const int b  = blockIdx.y;

    float xv[32];
    const size_t xbase = (((size_t)b * 32) * NN + n) * TT + t;
#pragma unroll
    for (int c = 0; c < 32; c++)
        xv[c] = x[xbase + (size_t)c * NN * TT];

    const size_t jrow0 = (size_t)n * JDIM + (size_t)b * 2048 + t;  // j at o=0

#pragma unroll 2
    for (int o = 0; o < 32; o++) {
        const float4* w4 = Ws4 + o * 24;
        float s0x = 0.f, s0y = 0.f, s0z = 0.f, s0w = 0.f;
        float s1x = 0.f, s1y = 0.f, s1z = 0.f, s1w = 0.f;
        float s2x = 0.f, s2y = 0.f, s2z = 0.f, s2w = 0.f;
#pragma unroll
        for (int q = 0; q < 8; q++) {
            const float x0 = xv[q * 4 + 0], x1 = xv[q * 4 + 1];
            const float x2 = xv[q * 4 + 2], x3 = xv[q * 4 + 3];
            const float4 w0 = w4[q];
            const float4 w1 = w4[8 + q];
            const float4 w2 = w4[16 + q];
            s0x += w0.x * x0; s0y += w0.y * x1; s0z += w0.z * x2; s0w += w0.w * x3;
            s1x += w1.x * x0; s1y += w1.y * x1; s1z += w1.z * x2; s1w += w1.w * x3;
            s2x += w2.x * x0; s2y += w2.y * x1; s2z += w2.z * x2; s2w += w2.w * x3;
        }
        const float a0 = (s0x + s0y) + (s0z + s0w);
        const float a1 = (s1x + s1y) + (s1z + s1w);
        const float a2 = (s2x + s2y) + (s2z + s2w);
        const size_t idx = jrow0 + (size_t)o * 64;
        U0[idx] = a0;
        __nv_bfloat162 p = __floats2bfloat162_rn(a1, a2);
        Uw2[idx] = *reinterpret_cast<uint32_t*>(&p);
    }
}

// ---------------------------------------------------------------------------
// Main GEMM (bf16 mma m16n8k16, ldmatrix A frags, 4-stage cp.async):
//   D[1024 x 32768] = Mb[1024 x 2048 bf16] @ U  (U packed bf16x2 pair rows)
//   out[bz][n][t] = D[n][j] + U0[n][j] + bias[bz & 31]
// ---------------------------------------------------------------------------
__global__ __launch_bounds__(256, 1) void main_gemm_bf16(
    const uint32_t* __restrict__ Mb2, const uint32_t* __restrict__ Uw2,
    const float* __restrict__ U0,     const float* __restrict__ bias,
    float* __restrict__ out)
{
    extern __shared__ __align__(1024) char smem[];
    const uint32_t sbase = smem_u32(smem);
    const uint32_t* smu = reinterpret_cast<uint32_t*>(smem);

    const int tid  = threadIdx.x;
    const int wid  = tid >> 5;
    const int lane = tid & 31;
    const int wm   = wid >> 1;
    const int wn   = wid & 1;
    const int qrow = lane >> 2;
    const int qcol = lane & 3;
    const int lrow = lane & 15;
    const int lkw  = (lane >> 4) << 2;

    const int row0 = blockIdx.x * BM;
    const int col0 = blockIdx.y * BN;

    float acc[4][8][4];
#pragma unroll
    for (int mt = 0; mt < 4; mt++)
#pragma unroll
        for (int nt = 0; nt < 8; nt++)
#pragma unroll
            for (int q = 0; q < 4; q++) acc[mt][nt][q] = 0.0f;

    const int a_row = tid >> 3;
    const int a_chk = tid & 7;
    const int b_k   = tid >> 5;
    const int b_chk = tid & 31;

    const char* gA = (const char*)Mb2 + (size_t)row0 * (NN * 4);
    const uint32_t* gB = Uw2 + col0;

#define MAIN_LOAD(it, slot)                                                          \
    do {                                                                             \
        const uint32_t sa = sbase + (slot) * STAGE_BYTES;                            \
        const uint32_t sb = sa + A_STAGE_BYTES;                                      \
        _Pragma("unroll")                                                            \
        for (int jj = 0; jj < 8; jj++) {                                             \
            const int r = a_row + jj * 32;                                           \
            cp_async16(sa + r * (LDAW * 4) + a_chk * 16,                             \
                       gA + (size_t)r * (NN * 4) + (it) * 128 + a_chk * 16);         \
        }                                                                            \
        _Pragma("unroll")                                                            \
        for (int jj = 0; jj < 4; jj++) {                                             \
            const int k = b_k + jj * 8;                                              \
            cp_async16(sb + k * (LDBW * 4) + b_chk * 16,                             \
                       gB + (size_t)((it) * 32 + k) * JDIM + b_chk * 4);             \
        }                                                                            \
    } while (0)

    MAIN_LOAD(0, 0); CP_COMMIT();
    MAIN_LOAD(1, 1); CP_COMMIT();
    MAIN_LOAD(2, 2); CP_COMMIT();

    int slot_c = 0;
    for (int it = 0; it < GEMM_ITERS; ++it) {
        CP_WAIT2();
        __syncthreads();
        if (it + 3 < GEMM_ITERS) MAIN_LOAD(it + 3, (it + 3) & 3);
        CP_COMMIT();

        const uint32_t As_b = sbase + slot_c * STAGE_BYTES;
        const uint32_t* Bs = smu + slot_c * (STAGE_BYTES / 4) + (A_STAGE_BYTES / 4);
        const int bcol_base = wn * 64 + qrow;
#pragma unroll
        for (int ks = 0; ks < 4; ks++) {
            const int kw = ks * 8 + qcol;
            uint32_t af[4][4];
#pragma unroll
            for (int mt = 0; mt < 4; mt++) {
                const uint32_t addr = As_b +
                    (uint32_t)(((wm * 64 + mt * 16 + lrow) * LDAW) + ks * 8 + lkw) * 4;
                ldsm_x4(af[mt], addr);
            }
            uint32_t bf[8][2];
#pragma unroll
            for (int nt = 0; nt < 8; nt++) {
                const uint32_t* bp = Bs + kw * LDBW + bcol_base + nt * 8;
                bf[nt][0] = bp[0];
                bf[nt][1] = bp[4 * LDBW];
            }
#pragma unroll
            for (int mt = 0; mt < 4; mt++)
#pragma unroll
                for (int nt = 0; nt < 8; nt++)
                    mma_bf16(acc[mt][nt], af[mt], bf[nt]);
        }
        slot_c = (slot_c + 1) & 3;
    }
#undef MAIN_LOAD

    // ---- epilogue: + U0 + bias, scatter to out[bz][n][t] ----
    const int j0 = col0 + wn * 64;
    const int bz = j0 >> 6;
    const float bv = bias[bz & 31];
#pragma unroll
    for (int mt = 0; mt < 4; mt++) {
#pragma unroll
        for (int h = 0; h < 2; h++) {
            const int n = row0 + wm * 64 + mt * 16 + h * 8 + qrow;
            float* orow = out + (size_t)bz * (NN * TT) + (size_t)n * TT;
            const float* u0row = U0 + (size_t)n * JDIM + j0;
#pragma unroll
            for (int nt = 0; nt < 8; nt++) {
                const int t = nt * 8 + qcol * 2;
                const float2 u = *reinterpret_cast<const float2*>(u0row + t);
                float2 v;
                v.x = acc[mt][nt][h * 2 + 0] + u.x + bv;
                v.y = acc[mt][nt][h * 2 + 1] + u.y + bv;
                *reinterpret_cast<float2*>(orow + t) = v;
            }
        }
    }
}

// ---------------------------------------------------------------------------
// Launch
// ---------------------------------------------------------------------------
extern "C" void kernel_launch(void* const* d_in, const int* in_sizes, int n_in,
                              void* d_out, int out_size)
{
    const float* x  = (const float*)d_in[0];
    const float* AL = (const float*)d_in[1];
    const float* AS = (const float*)d_in[2];
    const float* W  = (const float*)d_in[3];
    const float* bm = (const float*)d_in[4];
    float* out = (float*)d_out;

    uint32_t *pUw2, *pM2;
    float *pU0, *pG1, *pS, *pG2p, *pG1p;
    cudaGetSymbolAddress((void**)&pUw2, g_Uw2);
    cudaGetSymbolAddress((void**)&pU0,  g_U0);
    cudaGetSymbolAddress((void**)&pM2,  g_M2);
    cudaGetSymbolAddress((void**)&pG1,  g_G1);
    cudaGetSymbolAddress((void**)&pS,   g_S);
    cudaGetSymbolAddress((void**)&pG2p, g_G2p);
    cudaGetSymbolAddress((void**)&pG1p, g_G1p);

    cudaFuncSetAttribute(gemm_pre_tf32,
                         cudaFuncAttributeMaxDynamicSharedMemorySize, SMEM_PRE);
    cudaFuncSetAttribute(main_gemm_bf16,
                         cudaFuncAttributeMaxDynamicSharedMemorySize, SMEM_MAIN);

    const dim3 gpre(1024 / BM, 1024 / PRE_BN, 2);   // 4 x 16 x 2 = 128 CTAs

    // stage 1: G1 = AL^2 ; S = AS - AS*AL  (subtract fused into z=1 epilogue)
    gemm_pre_tf32<<<gpre, 256, SMEM_PRE>>>(AL, AS, AL, AL, pG1, pS, AS);

    // stage 2: G2p = AL*G1 (=AL^3) ; G1p = AS*S (=AS^2(I-AL))
    gemm_pre_tf32<<<gpre, 256, SMEM_PRE>>>(AL, AS, pG1, pS, pG2p, pG1p, nullptr);

    // M (bf16x2 interleaved): lo = G1+S (=M1), hi = G2p+G1p (=M2)
    ew_buildM<<<4096, 256>>>(pG1, pS, pG2p, pG1p, pM2);

    // channel mix: U0 fp32, (u1,u2) packed bf16x2
    chanmix_kernel<<<dim3(NN / 4, BB), 256>>>(x, W, pUw2, pU0);

    // main bf16 tensor GEMM + fused epilogue (row tiles fast => B reuse in L2)
    main_gemm_bf16<<<dim3(NN / BM, JDIM / BN), 256, SMEM_MAIN>>>(pM2, pUw2, pU0, bm, out);
}

// round 12
// speedup vs baseline: 5.7763x; 1.1563x over previous
#include <cuda_runtime.h>
#include <cuda_bf16.h>
#include <cstdint>

// ---------------------------------------------------------------------------
// Problem constants
// ---------------------------------------------------------------------------
#define NN   1024
#define TT   64
#define BB   16
#define JDIM 32768         // B*C_OUT*T = 512*64

// main GEMM tiling: CTA 256x128, 256 thr, 8 warps (4M x 2N)
#define BM 256
#define BN 128
#define LDAW 36                          // uint32 per A smem row (32 data + 4 pad)
#define LDBW 136                         // uint32 per B smem row (128 data + 8 pad)
#define A_STAGE_BYTES (BM * LDAW * 4)    // 36864
#define B_STAGE_BYTES (32 * LDBW * 4)    // 17408
#define STAGE_BYTES (A_STAGE_BYTES + B_STAGE_BYTES)   // 54272
#define SMEM_MAIN (4 * STAGE_BYTES)      // 217088
#define GEMM_ITERS 32    // pre: K=1024/BK32 ; main: K=2048 bf16 / BK64

// precompute GEMM tiling: CTA 256x64 (grid 4x16x2 = 128 CTAs)
#define PRE_BN 64
#define PRE_LDBW 72
#define PRE_B_STAGE (32 * PRE_LDBW * 4)
#define PRE_STAGE_BYTES (A_STAGE_BYTES + PRE_B_STAGE)
#define SMEM_PRE (3 * PRE_STAGE_BYTES)

// chanmix-mma tiling
#define CM_CHUNK 256                     // cols per chunk
#define CM_NCHUNKS 4                     // chunks per CTA
#define CM_LDX 264                       // floats per X smem row (256 + 8 pad)
#define CM_LDA 36
#define CM_A_BYTES (96 * CM_LDA * 4)     // 13824
#define CM_X_BYTES (32 * CM_LDX * 4)     // 33792
#define SMEM_CM (CM_A_BYTES + 3 * CM_X_BYTES)   // 115200

// ---------------------------------------------------------------------------
// Scratch (device globals; allocations are forbidden)
// ---------------------------------------------------------------------------
__device__ __align__(128) uint32_t g_Uw2[(size_t)NN * JDIM]; // [m][j] bf16x2 (u1,u2) 128MB
__device__ __align__(128) float    g_U0 [(size_t)NN * JDIM]; // [n][j] fp32           128MB
__device__ __align__(128) uint32_t g_M2 [NN * NN];           // [n][m] bf16x2 (M1,M2) 4MB
__device__ __align__(128) float g_G1 [NN * NN];   // AL^2
__device__ __align__(128) float g_S  [NN * NN];   // AS(I-AL)
__device__ __align__(128) float g_G2p[NN * NN];   // AL^3
__device__ __align__(128) float g_G1p[NN * NN];   // AS^2(I-AL)

// ---------------------------------------------------------------------------
// Helpers
// ---------------------------------------------------------------------------
__device__ __forceinline__ uint32_t smem_u32(const void* p) {
    uint32_t a;
    asm("{ .reg .u64 t; cvta.to.shared.u64 t, %1; cvt.u32.u64 %0, t; }" : "=r"(a) : "l"(p));
    return a;
}
__device__ __forceinline__ float to_tf32(float x) {
    float r; asm("cvt.rna.tf32.f32 %0, %1;" : "=f"(r) : "f"(x)); return r;
}
__device__ __forceinline__ void cp_async16(uint32_t saddr, const void* gaddr) {
    asm volatile("cp.async.cg.shared.global [%0], [%1], 16;" :: "r"(saddr), "l"(gaddr) : "memory");
}
#define CP_COMMIT() asm volatile("cp.async.commit_group;" ::: "memory")
#define CP_WAIT1()  asm volatile("cp.async.wait_group 1;" ::: "memory")
#define CP_WAIT2()  asm volatile("cp.async.wait_group 2;" ::: "memory")

__device__ __forceinline__ void mma_tf32(float* d, const uint32_t* a, const uint32_t* b) {
    asm volatile(
        "mma.sync.aligned.m16n8k8.row.col.f32.tf32.tf32.f32 "
        "{%0,%1,%2,%3}, {%4,%5,%6,%7}, {%8,%9}, {%0,%1,%2,%3};\n"
        : "+f"(d[0]), "+f"(d[1]), "+f"(d[2]), "+f"(d[3])
        : "r"(a[0]), "r"(a[1]), "r"(a[2]), "r"(a[3]), "r"(b[0]), "r"(b[1]));
}
__device__ __forceinline__ void mma_bf16(float* d, const uint32_t* a, const uint32_t* b) {
    asm volatile(
        "mma.sync.aligned.m16n8k16.row.col.f32.bf16.bf16.f32 "
        "{%0,%1,%2,%3}, {%4,%5,%6,%7}, {%8,%9}, {%0,%1,%2,%3};\n"
        : "+f"(d[0]), "+f"(d[1]), "+f"(d[2]), "+f"(d[3])
        : "r"(a[0]), "r"(a[1]), "r"(a[2]), "r"(a[3]), "r"(b[0]), "r"(b[1]));
}
__device__ __forceinline__ void ldsm_x4(uint32_t* r, uint32_t saddr) {
    asm volatile("ldmatrix.sync.aligned.m8n8.x4.shared.b16 {%0,%1,%2,%3}, [%4];"
                 : "=r"(r[0]), "=r"(r[1]), "=r"(r[2]), "=r"(r[3]) : "r"(saddr));
}

// ---------------------------------------------------------------------------
// M2d[idx] = bf16x2( X1+Y1 , X2+Y2 )   (lo = M1, hi = M2)
// ---------------------------------------------------------------------------
__global__ __launch_bounds__(256) void ew_buildM(
    const float* __restrict__ X1, const float* __restrict__ Y1,
    const float* __restrict__ X2, const float* __restrict__ Y2,
    uint32_t* __restrict__ M2d)
{
    int idx = blockIdx.x * 256 + threadIdx.x;
    __nv_bfloat162 v = __floats2bfloat162_rn(X1[idx] + Y1[idx], X2[idx] + Y2[idx]);
    M2d[idx] = *reinterpret_cast<uint32_t*>(&v);
}

// ---------------------------------------------------------------------------
// Precompute GEMM (tf32 mma, fp32 in/out):
//   z=0: C0 = A0 @ B0      z=1: C1 = A1 @ B1, or sub - A1@B1 if sub != 0
// CTA 256x64, 8 warps = 4M x 2N.
// ---------------------------------------------------------------------------
__global__ __launch_bounds__(256, 1) void gemm_pre_tf32(
    const float* __restrict__ A0, const float* __restrict__ A1,
    const float* __restrict__ B0, const float* __restrict__ B1,
    float* __restrict__ C0, float* __restrict__ C1,
    const float* __restrict__ sub)
{
    extern __shared__ __align__(1024) char smem[];
    const uint32_t sbase = smem_u32(smem);
    float* smf = reinterpret_cast<float*>(smem);

    const int tid  = threadIdx.x;
    const int wid  = tid >> 5;
    const int lane = tid & 31;
    const int wm   = wid >> 1;
    const int wn   = wid & 1;
    const int qrow = lane >> 2;
    const int qcol = lane & 3;

    const int row0 = blockIdx.x * BM;
    const int col0 = blockIdx.y * PRE_BN;
    const float* gA = (blockIdx.z ? A1 : A0) + (size_t)row0 * 1024;
    const float* gB = (blockIdx.z ? B1 : B0) + col0;
    float* gC = (blockIdx.z ? C1 : C0);
    const float* gSub = (blockIdx.z && sub) ? sub : nullptr;

    float acc[4][4][4];
#pragma unroll
    for (int mt = 0; mt < 4; mt++)
#pragma unroll
        for (int nt = 0; nt < 4; nt++)
#pragma unroll
            for (int q = 0; q < 4; q++) acc[mt][nt][q] = 0.0f;

    const int a_row = tid >> 3;
    const int a_chk = tid & 7;
    const int b_k   = tid >> 4;
    const int b_chk = tid & 15;

#define PRE_LOAD(it, slot)                                                           \
    do {                                                                             \
        const uint32_t sa = sbase + (slot) * PRE_STAGE_BYTES;                        \
        const uint32_t sb = sa + A_STAGE_BYTES;                                      \
        const int koff = (it) * 32;                                                  \
        _Pragma("unroll")                                                            \
        for (int jj = 0; jj < 8; jj++) {                                             \
            const int r = a_row + jj * 32;                                           \
            cp_async16(sa + r * (LDAW * 4) + a_chk * 16,                             \
                       gA + (size_t)r * 1024 + koff + a_chk * 4);                    \
        }                                                                            \
        _Pragma("unroll")                                                            \
        for (int jj = 0; jj < 2; jj++) {                                             \
            const int k = b_k + jj * 16;                                             \
            cp_async16(sb + k * (PRE_LDBW * 4) + b_chk * 16,                         \
                       gB + (size_t)(koff + k) * 1024 + b_chk * 4);                  \
        }                                                                            \
    } while (0)

    PRE_LOAD(0, 0); CP_COMMIT();
    PRE_LOAD(1, 1); CP_COMMIT();

    int slot_c = 0;
    for (int it = 0; it < GEMM_ITERS; ++it) {
        CP_WAIT1();
        __syncthreads();
        if (it + 2 < GEMM_ITERS) PRE_LOAD(it + 2, (it + 2) % 3);
        CP_COMMIT();

        const float* As = smf + slot_c * (PRE_STAGE_BYTES / 4);
        const float* Bs = As + (A_STAGE_BYTES / 4);
        const int arow_base = wm * 64 + qrow;
        const int bcol_base = wn * 32 + qrow;
#pragma unroll
        for (int ks = 0; ks < 4; ks++) {
            const int k0 = ks * 8;
            uint32_t af[4][4];
#pragma unroll
            for (int mt = 0; mt < 4; mt++) {
                const float* ap = As + (arow_base + mt * 16) * LDAW + k0 + qcol;
                af[mt][0] = __float_as_uint(ap[0]);
                af[mt][1] = __float_as_uint(ap[8 * LDAW]);
                af[mt][2] = __float_as_uint(ap[4]);
                af[mt][3] = __float_as_uint(ap[8 * LDAW + 4]);
            }
            uint32_t bf[4][2];
#pragma unroll
            for (int nt = 0; nt < 4; nt++) {
                const float* bp = Bs + (k0 + qcol) * PRE_LDBW + bcol_base + nt * 8;
                bf[nt][0] = __float_as_uint(bp[0]);
                bf[nt][1] = __float_as_uint(bp[4 * PRE_LDBW]);
            }
#pragma unroll
            for (int mt = 0; mt < 4; mt++)
#pragma unroll
                for (int nt = 0; nt < 4; nt++)
                    mma_tf32(acc[mt][nt], af[mt], bf[nt]);
        }
        slot_c = (slot_c + 1) % 3;
    }
#undef PRE_LOAD

#pragma unroll
    for (int mt = 0; mt < 4; mt++) {
#pragma unroll
        for (int h = 0; h < 2; h++) {
            const int n = row0 + wm * 64 + mt * 16 + h * 8 + qrow;
            const size_t base = (size_t)n * 1024 + col0 + wn * 32;
#pragma unroll
            for (int nt = 0; nt < 4; nt++) {
                float vx = acc[mt][nt][h * 2 + 0];
                float vy = acc[mt][nt][h * 2 + 1];
                const size_t off = base + nt * 8 + qcol * 2;
                if (gSub) {
                    const float2 s = *reinterpret_cast<const float2*>(gSub + off);
                    vx = s.x - vx; vy = s.y - vy;
                }
                *reinterpret_cast<float2*>(gC + off) = make_float2(vx, vy);
            }
        }
    }
}

// ---------------------------------------------------------------------------
// chanmix via tf32 mma:
//   A[96 x 32] built from W with row remap:
//     rows 0..31           : u0 rows, A[o][c]            = W[o][c]
//     rows 32+16*seg+i     : i<8 -> u1[o=seg*8+i] = W[o][32+c]
//                            i>=8 -> u2[o=seg*8+i-8] = W[o][64+c]
//   (so each m16 tile pairs u1[o] (top 8 rows) with u2[o] (bottom 8 rows);
//    mma acc (c0,c2) = (u1,u2) same o -> direct bf16x2 pack)
//   B = x[b] viewed as [32c x 65536 (n,t)] tile.
//   Outputs: U0[n][j] fp32, Uw2[n][j] bf16x2, j=(b*32+o)*64+t.
// Grid (64, 16): CTA = 4 chunks of 256 cols. 8 warps: wid>>1 = col slice
// (64 cols = one n), wid&1 = row group (rows 0-47 / 48-95).
// ---------------------------------------------------------------------------
__global__ __launch_bounds__(256, 1) void chanmix_mma(
    const float* __restrict__ x, const float* __restrict__ W,
    uint32_t* __restrict__ Uw2, float* __restrict__ U0)
{
    extern __shared__ __align__(1024) char smem[];
    float* As = reinterpret_cast<float*>(smem);
    const uint32_t sbase = smem_u32(smem);
    const uint32_t xs_base = sbase + CM_A_BYTES;

    const int tid  = threadIdx.x;
    const int wid  = tid >> 5;
    const int lane = tid & 31;
    const int qrow = lane >> 2;
    const int qcol = lane & 3;
    const int colslice = wid >> 1;   // 0..3
    const int mgroup   = wid & 1;    // 0: rows 0-47, 1: rows 48-95

    const int b = blockIdx.y;
    const int colbase0 = blockIdx.x * (CM_CHUNK * CM_NCHUNKS);

    // build A in smem: remap rows, rna-round, compensate tf32 truncation bias
    for (int idx = tid; idx < 96 * 32; idx += 256) {
        const int row = idx >> 5, c = idx & 31;
        int o, cin;
        if (row < 32) { o = row; cin = c; }
        else {
            const int seg = (row - 32) >> 4, i = (row - 32) & 15;
            o = seg * 8 + (i & 7);
            cin = ((i < 8) ? 32 : 64) + c;
        }
        As[row * CM_LDA + c] = to_tf32(W[o * 96 + cin] * 1.000344f);
    }

    const float* xb = x + (size_t)b * 32 * 65536;
    const int xrow = tid >> 3;      // 0..31 = c
    const int cpos = tid & 7;       // 16B chunk within 128B

#define CM_LOAD(ch, slot)                                                            \
    do {                                                                             \
        const uint32_t sx = xs_base + (slot) * CM_X_BYTES;                           \
        const float* gx = xb + (size_t)xrow * 65536 + colbase0 + (ch) * CM_CHUNK;    \
        _Pragma("unroll")                                                            \
        for (int jj = 0; jj < 8; jj++)                                               \
            cp_async16(sx + xrow * (CM_LDX * 4) + (cpos + jj * 8) * 16,              \
                       gx + (cpos + jj * 8) * 4);                                    \
    } while (0)

    CM_LOAD(0, 0); CP_COMMIT();
    CM_LOAD(1, 1); CP_COMMIT();
    __syncthreads();   // As built; stage0/1 in flight

    // preload all A fragments (constant across chunks)
    uint32_t af[3][4][4];
#pragma unroll
    for (int mt = 0; mt < 3; mt++) {
        const int rowb = mgroup * 48 + mt * 16 + qrow;
#pragma unroll
        for (int ks = 0; ks < 4; ks++) {
            const float* ap = As + rowb * CM_LDA + ks * 8 + qcol;
            af[mt][ks][0] = __float_as_uint(ap[0]);
            af[mt][ks][1] = __float_as_uint(ap[8 * CM_LDA]);
            af[mt][ks][2] = __float_as_uint(ap[4]);
            af[mt][ks][3] = __float_as_uint(ap[8 * CM_LDA + 4]);
        }
    }

    for (int ch = 0; ch < CM_NCHUNKS; ++ch) {
        CP_WAIT1();
        __syncthreads();
        if (ch + 2 < CM_NCHUNKS) CM_LOAD(ch + 2, (ch + 2) % 3);
        CP_COMMIT();

        const float* Xs = reinterpret_cast<const float*>(
            smem + CM_A_BYTES + (ch % 3) * CM_X_BYTES);

        float acc[3][8][4];
#pragma unroll
        for (int mt = 0; mt < 3; mt++)
#pragma unroll
            for (int nt = 0; nt < 8; nt++)
#pragma unroll
                for (int q = 0; q < 4; q++) acc[mt][nt][q] = 0.0f;

#pragma unroll
        for (int ks = 0; ks < 4; ks++) {
            uint32_t bf[8][2];
#pragma unroll
            for (int nt = 0; nt < 8; nt++) {
                const float* bp = Xs + (ks * 8 + qcol) * CM_LDX
                                  + colslice * 64 + nt * 8 + qrow;
                bf[nt][0] = __float_as_uint(bp[0]);
                bf[nt][1] = __float_as_uint(bp[4 * CM_LDX]);
            }
#pragma unroll
            for (int mt = 0; mt < 3; mt++)
#pragma unroll
                for (int nt = 0; nt < 8; nt++)
                    mma_tf32(acc[mt][nt], af[mt][ks], bf[nt]);
        }

        // epilogue: this warp's 64 cols = one n; t = nt*8 + 2*qcol (+1)
        const int col0 = colbase0 + ch * CM_CHUNK + colslice * 64;
        const int n = col0 >> 6;
        const size_t obase = (size_t)n * JDIM + (size_t)b * 2048;
#pragma unroll
        for (int mt = 0; mt < 3; mt++) {
            const int R = mgroup * 48 + mt * 16;
            if (R < 32) {
                // u0 tile: rows o = R+qrow and R+8+qrow, fp32 -> U0
#pragma unroll
                for (int h = 0; h < 2; h++) {
                    const int o = R + h * 8 + qrow;
                    float* dst = U0 + obase + (size_t)o * 64;
#pragma unroll
                    for (int nt = 0; nt < 8; nt++)
                        *reinterpret_cast<float2*>(dst + nt * 8 + qcol * 2) =
                            make_float2(acc[mt][nt][h * 2 + 0], acc[mt][nt][h * 2 + 1]);
                }
            } else {
                // paired tile: c0/c1 = u1[o], c2/c3 = u2[o]  -> bf16x2 -> Uw2
                const int seg = (R - 32) >> 4;
                const int o = seg * 8 + qrow;
                uint32_t* dst = Uw2 + obase + (size_t)o * 64;
#pragma unroll
                for (int nt = 0; nt < 8; nt++) {
                    __nv_bfloat162 p0 = __floats2bfloat162_rn(acc[mt][nt][0], acc[mt][nt][2]);
                    __nv_bfloat162 p1 = __floats2bfloat162_rn(acc[mt][nt][1], acc[mt][nt][3]);
                    uint2 v;
                    v.x = *reinterpret_cast<uint32_t*>(&p0);
                    v.y = *reinterpret_cast<uint32_t*>(&p1);
                    *reinterpret_cast<uint2*>(dst + nt * 8 + qcol * 2) = v;
                }
            }
        }
    }
#undef CM_LOAD
}

// ---------------------------------------------------------------------------
// Main GEMM (bf16 mma m16n8k16, ldmatrix A frags, 4-stage cp.async):
//   D[1024 x 32768] = Mb[1024 x 2048 bf16] @ U  (U packed bf16x2 pair rows)
//   out[bz][n][t] = D[n][j] + U0[n][j] + bias[bz & 31]
// ---------------------------------------------------------------------------
__global__ __launch_bounds__(256, 1) void main_gemm_bf16(
    const uint32_t* __restrict__ Mb2, const uint32_t* __restrict__ Uw2,
    const float* __restrict__ U0,     const float* __restrict__ bias,
    float* __restrict__ out)
{
    extern __shared__ __align__(1024) char smem[];
    const uint32_t sbase = smem_u32(smem);
    const uint32_t* smu = reinterpret_cast<uint32_t*>(smem);

    const int tid  = threadIdx.x;
    const int wid  = tid >> 5;
    const int lane = tid & 31;
    const int wm   = wid >> 1;
    const int wn   = wid & 1;
    const int qrow = lane >> 2;
    const int qcol = lane & 3;
    const int lrow = lane & 15;
    const int lkw  = (lane >> 4) << 2;

    const int row0 = blockIdx.x * BM;
    const int col0 = blockIdx.y * BN;

    float acc[4][8][4];
#pragma unroll
    for (int mt = 0; mt < 4; mt++)
#pragma unroll
        for (int nt = 0; nt < 8; nt++)
#pragma unroll
            for (int q = 0; q < 4; q++) acc[mt][nt][q] = 0.0f;

    const int a_row = tid >> 3;
    const int a_chk = tid & 7;
    const int b_k   = tid >> 5;
    const int b_chk = tid & 31;

    const char* gA = (const char*)Mb2 + (size_t)row0 * (NN * 4);
    const uint32_t* gB = Uw2 + col0;

#define MAIN_LOAD(it, slot)                                                          \
    do {                                                                             \
        const uint32_t sa = sbase + (slot) * STAGE_BYTES;                            \
        const uint32_t sb = sa + A_STAGE_BYTES;                                      \
        _Pragma("unroll")                                                            \
        for (int jj = 0; jj < 8; jj++) {                                             \
            const int r = a_row + jj * 32;                                           \
            cp_async16(sa + r * (LDAW * 4) + a_chk * 16,                             \
                       gA + (size_t)r * (NN * 4) + (it) * 128 + a_chk * 16);         \
        }                                                                            \
        _Pragma("unroll")                                                            \
        for (int jj = 0; jj < 4; jj++) {                                             \
            const int k = b_k + jj * 8;                                              \
            cp_async16(sb + k * (LDBW * 4) + b_chk * 16,                             \
                       gB + (size_t)((it) * 32 + k) * JDIM + b_chk * 4);             \
        }                                                                            \
    } while (0)

    MAIN_LOAD(0, 0); CP_COMMIT();
    MAIN_LOAD(1, 1); CP_COMMIT();
    MAIN_LOAD(2, 2); CP_COMMIT();

    int slot_c = 0;
    for (int it = 0; it < GEMM_ITERS; ++it) {
        CP_WAIT2();
        __syncthreads();
        if (it + 3 < GEMM_ITERS) MAIN_LOAD(it + 3, (it + 3) & 3);
        CP_COMMIT();

        const uint32_t As_b = sbase + slot_c * STAGE_BYTES;
        const uint32_t* Bs = smu + slot_c * (STAGE_BYTES / 4) + (A_STAGE_BYTES / 4);
        const int bcol_base = wn * 64 + qrow;
#pragma unroll
        for (int ks = 0; ks < 4; ks++) {
            const int kw = ks * 8 + qcol;
            uint32_t af[4][4];
#pragma unroll
            for (int mt = 0; mt < 4; mt++) {
                const uint32_t addr = As_b +
                    (uint32_t)(((wm * 64 + mt * 16 + lrow) * LDAW) + ks * 8 + lkw) * 4;
                ldsm_x4(af[mt], addr);
            }
            uint32_t bf[8][2];
#pragma unroll
            for (int nt = 0; nt < 8; nt++) {
                const uint32_t* bp = Bs + kw * LDBW + bcol_base + nt * 8;
                bf[nt][0] = bp[0];
                bf[nt][1] = bp[4 * LDBW];
            }
#pragma unroll
            for (int mt = 0; mt < 4; mt++)
#pragma unroll
                for (int nt = 0; nt < 8; nt++)
                    mma_bf16(acc[mt][nt], af[mt], bf[nt]);
        }
        slot_c = (slot_c + 1) & 3;
    }
#undef MAIN_LOAD

    // ---- epilogue: + U0 + bias, scatter to out[bz][n][t] ----
    const int j0 = col0 + wn * 64;
    const int bz = j0 >> 6;
    const float bv = bias[bz & 31];
#pragma unroll
    for (int mt = 0; mt < 4; mt++) {
#pragma unroll
        for (int h = 0; h < 2; h++) {
            const int n = row0 + wm * 64 + mt * 16 + h * 8 + qrow;
            float* orow = out + (size_t)bz * (NN * TT) + (size_t)n * TT;
            const float* u0row = U0 + (size_t)n * JDIM + j0;
#pragma unroll
            for (int nt = 0; nt < 8; nt++) {
                const int t = nt * 8 + qcol * 2;
                const float2 u = *reinterpret_cast<const float2*>(u0row + t);
                float2 v;
                v.x = acc[mt][nt][h * 2 + 0] + u.x + bv;
                v.y = acc[mt][nt][h * 2 + 1] + u.y + bv;
                *reinterpret_cast<float2*>(orow + t) = v;
            }
        }
    }
}

// ---------------------------------------------------------------------------
// Launch
// ---------------------------------------------------------------------------
extern "C" void kernel_launch(void* const* d_in, const int* in_sizes, int n_in,
                              void* d_out, int out_size)
{
    const float* x  = (const float*)d_in[0];
    const float* AL = (const float*)d_in[1];
    const float* AS = (const float*)d_in[2];
    const float* W  = (const float*)d_in[3];
    const float* bm = (const float*)d_in[4];
    float* out = (float*)d_out;

    uint32_t *pUw2, *pM2;
    float *pU0, *pG1, *pS, *pG2p, *pG1p;
    cudaGetSymbolAddress((void**)&pUw2, g_Uw2);
    cudaGetSymbolAddress((void**)&pU0,  g_U0);
    cudaGetSymbolAddress((void**)&pM2,  g_M2);
    cudaGetSymbolAddress((void**)&pG1,  g_G1);
    cudaGetSymbolAddress((void**)&pS,   g_S);
    cudaGetSymbolAddress((void**)&pG2p, g_G2p);
    cudaGetSymbolAddress((void**)&pG1p, g_G1p);

    cudaFuncSetAttribute(gemm_pre_tf32,
                         cudaFuncAttributeMaxDynamicSharedMemorySize, SMEM_PRE);
    cudaFuncSetAttribute(chanmix_mma,
                         cudaFuncAttributeMaxDynamicSharedMemorySize, SMEM_CM);
    cudaFuncSetAttribute(main_gemm_bf16,
                         cudaFuncAttributeMaxDynamicSharedMemorySize, SMEM_MAIN);

    const dim3 gpre(1024 / BM, 1024 / PRE_BN, 2);   // 4 x 16 x 2 = 128 CTAs

    // stage 1: G1 = AL^2 ; S = AS - AS*AL  (subtract fused into z=1 epilogue)
    gemm_pre_tf32<<<gpre, 256, SMEM_PRE>>>(AL, AS, AL, AL, pG1, pS, AS);

    // stage 2: G2p = AL*G1 (=AL^3) ; G1p = AS*S (=AS^2(I-AL))
    gemm_pre_tf32<<<gpre, 256, SMEM_PRE>>>(AL, AS, pG1, pS, pG2p, pG1p, nullptr);

    // M (bf16x2 interleaved): lo = G1+S (=M1), hi = G2p+G1p (=M2)
    ew_buildM<<<4096, 256>>>(pG1, pS, pG2p, pG1p, pM2);

    // channel mix on tensor cores: U0 fp32, (u1,u2) packed bf16x2
    chanmix_mma<<<dim3(65536 / (CM_CHUNK * CM_NCHUNKS), BB), 256, SMEM_CM>>>(
        x, W, pUw2, pU0);

    // main bf16 tensor GEMM + fused epilogue (row tiles fast => B reuse in L2)
    main_gemm_bf16<<<dim3(NN / BM, JDIM / BN), 256, SMEM_MAIN>>>(pM2, pUw2, pU0, bm, out);
}

// round 13
// speedup vs baseline: 5.8701x; 1.0162x over previous
#include <cuda_runtime.h>
#include <cuda_bf16.h>
#include <cstdint>

// ---------------------------------------------------------------------------
// Problem constants
// ---------------------------------------------------------------------------
#define NN   1024
#define TT   64
#define BB   16
#define JDIM 32768         // B*C_OUT*T = 512*64

// main GEMM tiling: CTA 256x128, 256 thr, 8 warps (4M x 2N)
#define BM 256
#define BN 128
#define LDAW 36                          // uint32 per A smem row (32 data + 4 pad)
#define LDBW 136                         // uint32 per B smem row (128 data + 8 pad)
#define A_STAGE_BYTES (BM * LDAW * 4)    // 36864
#define B_STAGE_BYTES (32 * LDBW * 4)    // 17408
#define STAGE_BYTES (A_STAGE_BYTES + B_STAGE_BYTES)   // 54272
#define SMEM_MAIN (4 * STAGE_BYTES)      // 217088
#define GEMM_ITERS 32    // pre: K=1024/BK32 ; main: K=2048 bf16 / BK64

// precompute GEMM tiling: CTA 256x64 (grid 4x16x2 = 128 CTAs)
#define PRE_BN 64
#define PRE_LDBW 72
#define PRE_B_STAGE (32 * PRE_LDBW * 4)
#define PRE_STAGE_BYTES (A_STAGE_BYTES + PRE_B_STAGE)
#define SMEM_PRE (3 * PRE_STAGE_BYTES)

// chanmix-mma tiling (512 threads, 16 warps = 8 colslices x 2 rowgroups)
#define CM_CHUNK 256                     // cols per chunk
#define CM_NCHUNKS 4                     // chunks per CTA
#define CM_LDX 264                       // floats per X smem row (256 + 8 pad)
#define CM_LDA 36
#define CM_A_BYTES (96 * CM_LDA * 4)     // 13824
#define CM_X_BYTES (32 * CM_LDX * 4)     // 33792
#define SMEM_CM (CM_A_BYTES + 3 * CM_X_BYTES)   // 115200

// ---------------------------------------------------------------------------
// Scratch (device globals; allocations are forbidden)
// ---------------------------------------------------------------------------
__device__ __align__(128) uint32_t g_Uw2[(size_t)NN * JDIM]; // [m][j] bf16x2 (u1,u2) 128MB
__device__ __align__(128) float    g_U0 [(size_t)NN * JDIM]; // [n][j] fp32           128MB
__device__ __align__(128) uint32_t g_M2 [NN * NN];           // [n][m] bf16x2 (M1,M2) 4MB
__device__ __align__(128) float g_G1 [NN * NN];   // AL^2
__device__ __align__(128) float g_S  [NN * NN];   // AS(I-AL)
__device__ __align__(128) float g_G2p[NN * NN];   // AL^3
__device__ __align__(128) float g_G1p[NN * NN];   // AS^2(I-AL)
__device__ int g_sink;

// ---------------------------------------------------------------------------
// Helpers
// ---------------------------------------------------------------------------
__device__ __forceinline__ uint32_t smem_u32(const void* p) {
    uint32_t a;
    asm("{ .reg .u64 t; cvta.to.shared.u64 t, %1; cvt.u32.u64 %0, t; }" : "=r"(a) : "l"(p));
    return a;
}
__device__ __forceinline__ float to_tf32(float x) {
    float r; asm("cvt.rna.tf32.f32 %0, %1;" : "=f"(r) : "f"(x)); return r;
}
__device__ __forceinline__ void cp_async16(uint32_t saddr, const void* gaddr) {
    asm volatile("cp.async.cg.shared.global [%0], [%1], 16;" :: "r"(saddr), "l"(gaddr) : "memory");
}
#define CP_COMMIT() asm volatile("cp.async.commit_group;" ::: "memory")
#define CP_WAIT1()  asm volatile("cp.async.wait_group 1;" ::: "memory")
#define CP_WAIT2()  asm volatile("cp.async.wait_group 2;" ::: "memory")

__device__ __forceinline__ void mma_tf32(float* d, const uint32_t* a, const uint32_t* b) {
    asm volatile(
        "mma.sync.aligned.m16n8k8.row.col.f32.tf32.tf32.f32 "
        "{%0,%1,%2,%3}, {%4,%5,%6,%7}, {%8,%9}, {%0,%1,%2,%3};\n"
        : "+f"(d[0]), "+f"(d[1]), "+f"(d[2]), "+f"(d[3])
        : "r"(a[0]), "r"(a[1]), "r"(a[2]), "r"(a[3]), "r"(b[0]), "r"(b[1]));
}
__device__ __forceinline__ void mma_bf16(float* d, const uint32_t* a, const uint32_t* b) {
    asm volatile(
        "mma.sync.aligned.m16n8k16.row.col.f32.bf16.bf16.f32 "
        "{%0,%1,%2,%3}, {%4,%5,%6,%7}, {%8,%9}, {%0,%1,%2,%3};\n"
        : "+f"(d[0]), "+f"(d[1]), "+f"(d[2]), "+f"(d[3])
        : "r"(a[0]), "r"(a[1]), "r"(a[2]), "r"(a[3]), "r"(b[0]), "r"(b[1]));
}
__device__ __forceinline__ void ldsm_x4(uint32_t* r, uint32_t saddr) {
    asm volatile("ldmatrix.sync.aligned.m8n8.x4.shared.b16 {%0,%1,%2,%3}, [%4];"
                 : "=r"(r[0]), "=r"(r[1]), "=r"(r[2]), "=r"(r[3]) : "r"(saddr));
}

// no-op phase-shift kernel so ncu (-s 5 -c 1) profiles main_gemm_bf16
__global__ void dummy_kernel(int* sink) { if (threadIdx.x == 1024) *sink = 1; }

// ---------------------------------------------------------------------------
// M2d[idx] = bf16x2( X1+Y1 , X2+Y2 )   (lo = M1, hi = M2)
// ---------------------------------------------------------------------------
__global__ __launch_bounds__(256) void ew_buildM(
    const float* __restrict__ X1, const float* __restrict__ Y1,
    const float* __restrict__ X2, const float* __restrict__ Y2,
    uint32_t* __restrict__ M2d)
{
    int idx = blockIdx.x * 256 + threadIdx.x;
    __nv_bfloat162 v = __floats2bfloat162_rn(X1[idx] + Y1[idx], X2[idx] + Y2[idx]);
    M2d[idx] = *reinterpret_cast<uint32_t*>(&v);
}

// ---------------------------------------------------------------------------
// Precompute GEMM (tf32 mma, fp32 in/out):
//   z=0: C0 = A0 @ B0      z=1: C1 = A1 @ B1, or sub - A1@B1 if sub != 0
// ---------------------------------------------------------------------------
__global__ __launch_bounds__(256, 1) void gemm_pre_tf32(
    const float* __restrict__ A0, const float* __restrict__ A1,
    const float* __restrict__ B0, const float* __restrict__ B1,
    float* __restrict__ C0, float* __restrict__ C1,
    const float* __restrict__ sub)
{
    extern __shared__ __align__(1024) char smem[];
    const uint32_t sbase = smem_u32(smem);
    float* smf = reinterpret_cast<float*>(smem);

    const int tid  = threadIdx.x;
    const int wid  = tid >> 5;
    const int lane = tid & 31;
    const int wm   = wid >> 1;
    const int wn   = wid & 1;
    const int qrow = lane >> 2;
    const int qcol = lane & 3;

    const int row0 = blockIdx.x * BM;
    const int col0 = blockIdx.y * PRE_BN;
    const float* gA = (blockIdx.z ? A1 : A0) + (size_t)row0 * 1024;
    const float* gB = (blockIdx.z ? B1 : B0) + col0;
    float* gC = (blockIdx.z ? C1 : C0);
    const float* gSub = (blockIdx.z && sub) ? sub : nullptr;

    float acc[4][4][4];
#pragma unroll
    for (int mt = 0; mt < 4; mt++)
#pragma unroll
        for (int nt = 0; nt < 4; nt++)
#pragma unroll
            for (int q = 0; q < 4; q++) acc[mt][nt][q] = 0.0f;

    const int a_row = tid >> 3;
    const int a_chk = tid & 7;
    const int b_k   = tid >> 4;
    const int b_chk = tid & 15;

#define PRE_LOAD(it, slot)                                                           \
    do {                                                                             \
        const uint32_t sa = sbase + (slot) * PRE_STAGE_BYTES;                        \
        const uint32_t sb = sa + A_STAGE_BYTES;                                      \
        const int koff = (it) * 32;                                                  \
        _Pragma("unroll")                                                            \
        for (int jj = 0; jj < 8; jj++) {                                             \
            const int r = a_row + jj * 32;                                           \
            cp_async16(sa + r * (LDAW * 4) + a_chk * 16,                             \
                       gA + (size_t)r * 1024 + koff + a_chk * 4);                    \
        }                                                                            \
        _Pragma("unroll")                                                            \
        for (int jj = 0; jj < 2; jj++) {                                             \
            const int k = b_k + jj * 16;                                             \
            cp_async16(sb + k * (PRE_LDBW * 4) + b_chk * 16,                         \
                       gB + (size_t)(koff + k) * 1024 + b_chk * 4);                  \
        }                                                                            \
    } while (0)

    PRE_LOAD(0, 0); CP_COMMIT();
    PRE_LOAD(1, 1); CP_COMMIT();

    int slot_c = 0;
    for (int it = 0; it < GEMM_ITERS; ++it) {
        CP_WAIT1();
        __syncthreads();
        if (it + 2 < GEMM_ITERS) PRE_LOAD(it + 2, (it + 2) % 3);
        CP_COMMIT();

        const float* As = smf + slot_c * (PRE_STAGE_BYTES / 4);
        const float* Bs = As + (A_STAGE_BYTES / 4);
        const int arow_base = wm * 64 + qrow;
        const int bcol_base = wn * 32 + qrow;
#pragma unroll
        for (int ks = 0; ks < 4; ks++) {
            const int k0 = ks * 8;
            uint32_t af[4][4];
#pragma unroll
            for (int mt = 0; mt < 4; mt++) {
                const float* ap = As + (arow_base + mt * 16) * LDAW + k0 + qcol;
                af[mt][0] = __float_as_uint(ap[0]);
                af[mt][1] = __float_as_uint(ap[8 * LDAW]);
                af[mt][2] = __float_as_uint(ap[4]);
                af[mt][3] = __float_as_uint(ap[8 * LDAW + 4]);
            }
            uint32_t bf[4][2];
#pragma unroll
            for (int nt = 0; nt < 4; nt++) {
                const float* bp = Bs + (k0 + qcol) * PRE_LDBW + bcol_base + nt * 8;
                bf[nt][0] = __float_as_uint(bp[0]);
                bf[nt][1] = __float_as_uint(bp[4 * PRE_LDBW]);
            }
#pragma unroll
            for (int mt = 0; mt < 4; mt++)
#pragma unroll
                for (int nt = 0; nt < 4; nt++)
                    mma_tf32(acc[mt][nt], af[mt], bf[nt]);
        }
        slot_c = (slot_c + 1) % 3;
    }
#undef PRE_LOAD

#pragma unroll
    for (int mt = 0; mt < 4; mt++) {
#pragma unroll
        for (int h = 0; h < 2; h++) {
            const int n = row0 + wm * 64 + mt * 16 + h * 8 + qrow;
            const size_t base = (size_t)n * 1024 + col0 + wn * 32;
#pragma unroll
            for (int nt = 0; nt < 4; nt++) {
                float vx = acc[mt][nt][h * 2 + 0];
                float vy = acc[mt][nt][h * 2 + 1];
                const size_t off = base + nt * 8 + qcol * 2;
                if (gSub) {
                    const float2 s = *reinterpret_cast<const float2*>(gSub + off);
                    vx = s.x - vx; vy = s.y - vy;
                }
                *reinterpret_cast<float2*>(gC + off) = make_float2(vx, vy);
            }
        }
    }
}

// ---------------------------------------------------------------------------
// chanmix via tf32 mma (512 threads, 16 warps):
//   A[96 x 32] from W, row remap: rows 0..31 = u0; rows 32+16*seg+i pair
//   u1[o] (i<8) with u2[o] (i>=8), o = seg*8 + (i&7)  -> acc (c0,c2) = (u1,u2)
//   B = x[b] as [32c x 65536 (n,t)].  Outputs U0 fp32, Uw2 bf16x2.
// Warp layout: colslice = wid>>1 (8 slices x 32 cols), mgroup = wid&1
// (rows 0-47 / 48-95).  acc[3][4][4], af[3][4][4] -> ~120 regs.
// ---------------------------------------------------------------------------
__global__ __launch_bounds__(512, 1) void chanmix_mma(
    const float* __restrict__ x, const float* __restrict__ W,
    uint32_t* __restrict__ Uw2, float* __restrict__ U0)
{
    extern __shared__ __align__(1024) char smem[];
    float* As = reinterpret_cast<float*>(smem);
    const uint32_t sbase = smem_u32(smem);
    const uint32_t xs_base = sbase + CM_A_BYTES;

    const int tid  = threadIdx.x;
    const int wid  = tid >> 5;
    const int lane = tid & 31;
    const int qrow = lane >> 2;
    const int qcol = lane & 3;
    const int colslice = wid >> 1;   // 0..7  (32 cols each)
    const int mgroup   = wid & 1;    // 0: rows 0-47, 1: rows 48-95

    const int b = blockIdx.y;
    const int colbase0 = blockIdx.x * (CM_CHUNK * CM_NCHUNKS);

    // build A in smem: remap rows, rna-round, compensate tf32 truncation bias
    for (int idx = tid; idx < 96 * 32; idx += 512) {
        const int row = idx >> 5, c = idx & 31;
        int o, cin;
        if (row < 32) { o = row; cin = c; }
        else {
            const int seg = (row - 32) >> 4, i = (row - 32) & 15;
            o = seg * 8 + (i & 7);
            cin = ((i < 8) ? 32 : 64) + c;
        }
        As[row * CM_LDA + c] = to_tf32(W[o * 96 + cin] * 1.000344f);
    }

    const float* xb = x + (size_t)b * 32 * 65536;
    const int xrow = tid >> 4;      // 0..31 = c
    const int cpos = tid & 15;      // 16B chunk group

#define CM_LOAD(ch, slot)                                                            \
    do {                                                                             \
        const uint32_t sx = xs_base + (slot) * CM_X_BYTES;                           \
        const float* gx = xb + (size_t)xrow * 65536 + colbase0 + (ch) * CM_CHUNK;    \
        _Pragma("unroll")                                                            \
        for (int jj = 0; jj < 4; jj++)                                               \
            cp_async16(sx + xrow * (CM_LDX * 4) + (cpos + jj * 16) * 16,             \
                       gx + (cpos + jj * 16) * 4);                                   \
    } while (0)

    CM_LOAD(0, 0); CP_COMMIT();
    CM_LOAD(1, 1); CP_COMMIT();
    __syncthreads();   // As built; stage0/1 in flight

    // preload A fragments (constant across chunks)
    uint32_t af[3][4][4];
#pragma unroll
    for (int mt = 0; mt < 3; mt++) {
        const int rowb = mgroup * 48 + mt * 16 + qrow;
#pragma unroll
        for (int ks = 0; ks < 4; ks++) {
            const float* ap = As + rowb * CM_LDA + ks * 8 + qcol;
            af[mt][ks][0] = __float_as_uint(ap[0]);
            af[mt][ks][1] = __float_as_uint(ap[8 * CM_LDA]);
            af[mt][ks][2] = __float_as_uint(ap[4]);
            af[mt][ks][3] = __float_as_uint(ap[8 * CM_LDA + 4]);
        }
    }

    for (int ch = 0; ch < CM_NCHUNKS; ++ch) {
        CP_WAIT1();
        __syncthreads();
        if (ch + 2 < CM_NCHUNKS) CM_LOAD(ch + 2, (ch + 2) % 3);
        CP_COMMIT();

        const float* Xs = reinterpret_cast<const float*>(
            smem + CM_A_BYTES + (ch % 3) * CM_X_BYTES);

        float acc[3][4][4];
#pragma unroll
        for (int mt = 0; mt < 3; mt++)
#pragma unroll
            for (int nt = 0; nt < 4; nt++)
#pragma unroll
                for (int q = 0; q < 4; q++) acc[mt][nt][q] = 0.0f;

#pragma unroll
        for (int ks = 0; ks < 4; ks++) {
            uint32_t bf[4][2];
#pragma unroll
            for (int nt = 0; nt < 4; nt++) {
                const float* bp = Xs + (ks * 8 + qcol) * CM_LDX
                                  + colslice * 32 + nt * 8 + qrow;
                bf[nt][0] = __float_as_uint(bp[0]);
                bf[nt][1] = __float_as_uint(bp[4 * CM_LDX]);
            }
#pragma unroll
            for (int mt = 0; mt < 3; mt++)
#pragma unroll
                for (int nt = 0; nt < 4; nt++)
                    mma_tf32(acc[mt][nt], af[mt][ks], bf[nt]);
        }

        // epilogue: this warp's 32 cols = half of one n (t in [tb, tb+32))
        const int col0 = colbase0 + ch * CM_CHUNK + colslice * 32;
        const int n  = col0 >> 6;
        const int tb = col0 & 63;   // 0 or 32
        const size_t obase = (size_t)n * JDIM + (size_t)b * 2048 + tb;
#pragma unroll
        for (int mt = 0; mt < 3; mt++) {
            const int R = mgroup * 48 + mt * 16;
            if (R < 32) {
#pragma unroll
                for (int h = 0; h < 2; h++) {
                    const int o = R + h * 8 + qrow;
                    float* dst = U0 + obase + (size_t)o * 64;
#pragma unroll
                    for (int nt = 0; nt < 4; nt++)
                        *reinterpret_cast<float2*>(dst + nt * 8 + qcol * 2) =
                            make_float2(acc[mt][nt][h * 2 + 0], acc[mt][nt][h * 2 + 1]);
                }
            } else {
                const int seg = (R - 32) >> 4;
                const int o = seg * 8 + qrow;
                uint32_t* dst = Uw2 + obase + (size_t)o * 64;
#pragma unroll
                for (int nt = 0; nt < 4; nt++) {
                    __nv_bfloat162 p0 = __floats2bfloat162_rn(acc[mt][nt][0], acc[mt][nt][2]);
                    __nv_bfloat162 p1 = __floats2bfloat162_rn(acc[mt][nt][1], acc[mt][nt][3]);
                    uint2 v;
                    v.x = *reinterpret_cast<uint32_t*>(&p0);
                    v.y = *reinterpret_cast<uint32_t*>(&p1);
                    *reinterpret_cast<uint2*>(dst + nt * 8 + qcol * 2) = v;
                }
            }
        }
    }
#undef CM_LOAD
}

// ---------------------------------------------------------------------------
// Main GEMM (bf16 mma m16n8k16, ldmatrix A frags, 4-stage cp.async):
//   D[1024 x 32768] = Mb[1024 x 2048 bf16] @ U  (U packed bf16x2 pair rows)
//   out[bz][n][t] = D[n][j] + U0[n][j] + bias[bz & 31]
// ---------------------------------------------------------------------------
__global__ __launch_bounds__(256, 1) void main_gemm_bf16(
    const uint32_t* __restrict__ Mb2, const uint32_t* __restrict__ Uw2,
    const float* __restrict__ U0,     const float* __restrict__ bias,
    float* __restrict__ out)
{
    extern __shared__ __align__(1024) char smem[];
    const uint32_t sbase = smem_u32(smem);
    const uint32_t* smu = reinterpret_cast<uint32_t*>(smem);

    const int tid  = threadIdx.x;
    const int wid  = tid >> 5;
    const int lane = tid & 31;
    const int wm   = wid >> 1;
    const int wn   = wid & 1;
    const int qrow = lane >> 2;
    const int qcol = lane & 3;
    const int lrow = lane & 15;
    const int lkw  = (lane >> 4) << 2;

    const int row0 = blockIdx.x * BM;
    const int col0 = blockIdx.y * BN;

    float acc[4][8][4];
#pragma unroll
    for (int mt = 0; mt < 4; mt++)
#pragma unroll
        for (int nt = 0; nt < 8; nt++)
#pragma unroll
            for (int q = 0; q < 4; q++) acc[mt][nt][q] = 0.0f;

    const int a_row = tid >> 3;
    const int a_chk = tid & 7;
    const int b_k   = tid >> 5;
    const int b_chk = tid & 31;

    const char* gA = (const char*)Mb2 + (size_t)row0 * (NN * 4);
    const uint32_t* gB = Uw2 + col0;

#define MAIN_LOAD(it, slot)                                                          \
    do {                                                                             \
        const uint32_t sa = sbase + (slot) * STAGE_BYTES;                            \
        const uint32_t sb = sa + A_STAGE_BYTES;                                      \
        _Pragma("unroll")                                                            \
        for (int jj = 0; jj < 8; jj++) {                                             \
            const int r = a_row + jj * 32;                                           \
            cp_async16(sa + r * (LDAW * 4) + a_chk * 16,                             \
                       gA + (size_t)r * (NN * 4) + (it) * 128 + a_chk * 16);         \
        }                                                                            \
        _Pragma("unroll")                                                            \
        for (int jj = 0; jj < 4; jj++) {                                             \
            const int k = b_k + jj * 8;                                              \
            cp_async16(sb + k * (LDBW * 4) + b_chk * 16,                             \
                       gB + (size_t)((it) * 32 + k) * JDIM + b_chk * 4);             \
        }                                                                            \
    } while (0)

    MAIN_LOAD(0, 0); CP_COMMIT();
    MAIN_LOAD(1, 1); CP_COMMIT();
    MAIN_LOAD(2, 2); CP_COMMIT();

    int slot_c = 0;
    for (int it = 0; it < GEMM_ITERS; ++it) {
        CP_WAIT2();
        __syncthreads();
        if (it + 3 < GEMM_ITERS) MAIN_LOAD(it + 3, (it + 3) & 3);
        CP_COMMIT();

        const uint32_t As_b = sbase + slot_c * STAGE_BYTES;
        const uint32_t* Bs = smu + slot_c * (STAGE_BYTES / 4) + (A_STAGE_BYTES / 4);
        const int bcol_base = wn * 64 + qrow;
#pragma unroll
        for (int ks = 0; ks < 4; ks++) {
            const int kw = ks * 8 + qcol;
            uint32_t af[4][4];
#pragma unroll
            for (int mt = 0; mt < 4; mt++) {
                const uint32_t addr = As_b +
                    (uint32_t)(((wm * 64 + mt * 16 + lrow) * LDAW) + ks * 8 + lkw) * 4;
                ldsm_x4(af[mt], addr);
            }
            uint32_t bf[8][2];
#pragma unroll
            for (int nt = 0; nt < 8; nt++) {
                const uint32_t* bp = Bs + kw * LDBW + bcol_base + nt * 8;
                bf[nt][0] = bp[0];
                bf[nt][1] = bp[4 * LDBW];
            }
#pragma unroll
            for (int mt = 0; mt < 4; mt++)
#pragma unroll
                for (int nt = 0; nt < 8; nt++)
                    mma_bf16(acc[mt][nt], af[mt], bf[nt]);
        }
        slot_c = (slot_c + 1) & 3;
    }
#undef MAIN_LOAD

    // ---- epilogue: + U0 + bias, scatter to out[bz][n][t] ----
    const int j0 = col0 + wn * 64;
    const int bz = j0 >> 6;
    const float bv = bias[bz & 31];
#pragma unroll
    for (int mt = 0; mt < 4; mt++) {
#pragma unroll
        for (int h = 0; h < 2; h++) {
            const int n = row0 + wm * 64 + mt * 16 + h * 8 + qrow;
            float* orow = out + (size_t)bz * (NN * TT) + (size_t)n * TT;
            const float* u0row = U0 + (size_t)n * JDIM + j0;
#pragma unroll
            for (int nt = 0; nt < 8; nt++) {
                const int t = nt * 8 + qcol * 2;
                const float2 u = *reinterpret_cast<const float2*>(u0row + t);
                float2 v;
                v.x = acc[mt][nt][h * 2 + 0] + u.x + bv;
                v.y = acc[mt][nt][h * 2 + 1] + u.y + bv;
                *reinterpret_cast<float2*>(orow + t) = v;
            }
        }
    }
}

// ---------------------------------------------------------------------------
// Launch
// ---------------------------------------------------------------------------
extern "C" void kernel_launch(void* const* d_in, const int* in_sizes, int n_in,
                              void* d_out, int out_size)
{
    const float* x  = (const float*)d_in[0];
    const float* AL = (const float*)d_in[1];
    const float* AS = (const float*)d_in[2];
    const float* W  = (const float*)d_in[3];
    const float* bm = (const float*)d_in[4];
    float* out = (float*)d_out;

    uint32_t *pUw2, *pM2;
    float *pU0, *pG1, *pS, *pG2p, *pG1p;
    int* pSink;
    cudaGetSymbolAddress((void**)&pUw2, g_Uw2);
    cudaGetSymbolAddress((void**)&pU0,  g_U0);
    cudaGetSymbolAddress((void**)&pM2,  g_M2);
    cudaGetSymbolAddress((void**)&pG1,  g_G1);
    cudaGetSymbolAddress((void**)&pS,   g_S);
    cudaGetSymbolAddress((void**)&pG2p, g_G2p);
    cudaGetSymbolAddress((void**)&pG1p, g_G1p);
    cudaGetSymbolAddress((void**)&pSink, g_sink);

    cudaFuncSetAttribute(gemm_pre_tf32,
                         cudaFuncAttributeMaxDynamicSharedMemorySize, SMEM_PRE);
    cudaFuncSetAttribute(chanmix_mma,
                         cudaFuncAttributeMaxDynamicSharedMemorySize, SMEM_CM);
    cudaFuncSetAttribute(main_gemm_bf16,
                         cudaFuncAttributeMaxDynamicSharedMemorySize, SMEM_MAIN);

    // phase-shift launch #1 so ncu -s 5 profiles main_gemm_bf16 (launch #6)
    dummy_kernel<<<1, 32>>>(pSink);

    const dim3 gpre(1024 / BM, 1024 / PRE_BN, 2);   // 4 x 16 x 2 = 128 CTAs

    // stage 1: G1 = AL^2 ; S = AS - AS*AL  (subtract fused into z=1 epilogue)
    gemm_pre_tf32<<<gpre, 256, SMEM_PRE>>>(AL, AS, AL, AL, pG1, pS, AS);

    // stage 2: G2p = AL*G1 (=AL^3) ; G1p = AS*S (=AS^2(I-AL))
    gemm_pre_tf32<<<gpre, 256, SMEM_PRE>>>(AL, AS, pG1, pS, pG2p, pG1p, nullptr);

    // M (bf16x2 interleaved): lo = G1+S (=M1), hi = G2p+G1p (=M2)
    ew_buildM<<<4096, 256>>>(pG1, pS, pG2p, pG1p, pM2);

    // channel mix on tensor cores: U0 fp32, (u1,u2) packed bf16x2
    chanmix_mma<<<dim3(65536 / (CM_CHUNK * CM_NCHUNKS), BB), 512, SMEM_CM>>>(
        x, W, pUw2, pU0);

    // main bf16 tensor GEMM + fused epilogue (row tiles fast => B reuse in L2)
    main_gemm_bf16<<<dim3(NN / BM, JDIM / BN), 256, SMEM_MAIN>>>(pM2, pUw2, pU0, bm, out);
}

// round 14
// speedup vs baseline: 6.0965x; 1.0386x over previous
#include <cuda_runtime.h>
#include <cuda_bf16.h>
#include <cstdint>

// ---------------------------------------------------------------------------
// Problem constants
// ---------------------------------------------------------------------------
#define NN   1024
#define TT   64
#define BB   16
#define JDIM 32768         // B*C_OUT*T = 512*64

// main GEMM tiling: CTA 128x128, 256 thr, 8 warps (4M x 2N), 2 CTAs/SM
#define BM 128
#define BN 128
#define LDAW 36                          // uint32 per A smem row (32 data + 4 pad)
#define LDBW 136                         // uint32 per B smem row (128 data + 8 pad)
#define A_STAGE_BYTES (BM * LDAW * 4)    // 18432
#define B_STAGE_BYTES (32 * LDBW * 4)    // 17408
#define STAGE_BYTES (A_STAGE_BYTES + B_STAGE_BYTES)   // 35840
#define SMEM_MAIN (3 * STAGE_BYTES)      // 107520  (2 CTAs/SM fit in 228KB)
#define GEMM_ITERS 32    // pre: K=1024/BK32 ; main: K=2048 bf16 / BK64

// precompute GEMM tiling: CTA 256x64 (grid 4x16x2 = 128 CTAs)
#define PRE_BM 256
#define PRE_BN 64
#define PRE_LDBW 72
#define PRE_A_BYTES (PRE_BM * LDAW * 4)  // 36864
#define PRE_B_STAGE (32 * PRE_LDBW * 4)  // 9216
#define PRE_STAGE_BYTES (PRE_A_BYTES + PRE_B_STAGE)   // 46080
#define SMEM_PRE (3 * PRE_STAGE_BYTES)                 // 138240

// chanmix-mma tiling (512 threads, 16 warps = 8 colslices x 2 rowgroups)
#define CM_CHUNK 256
#define CM_NCHUNKS 4
#define CM_LDX 264
#define CM_LDA 36
#define CM_A_BYTES (96 * CM_LDA * 4)     // 13824
#define CM_X_BYTES (32 * CM_LDX * 4)     // 33792
#define SMEM_CM (CM_A_BYTES + 3 * CM_X_BYTES)   // 115200

// ---------------------------------------------------------------------------
// Scratch (device globals; allocations are forbidden)
// ---------------------------------------------------------------------------
__device__ __align__(128) uint32_t g_Uw2[(size_t)NN * JDIM]; // [m][j] bf16x2 (u1,u2) 128MB
__device__ __align__(128) float    g_U0 [(size_t)NN * JDIM]; // [n][j] fp32           128MB
__device__ __align__(128) uint32_t g_M2 [NN * NN];           // [n][m] bf16x2 (M1,M2) 4MB
__device__ __align__(128) float g_G1 [NN * NN];   // AL^2
__device__ __align__(128) float g_S  [NN * NN];   // AS(I-AL)
__device__ __align__(128) float g_G2p[NN * NN];   // AL^3
__device__ __align__(128) float g_G1p[NN * NN];   // AS^2(I-AL)

// ---------------------------------------------------------------------------
// Helpers
// ---------------------------------------------------------------------------
__device__ __forceinline__ uint32_t smem_u32(const void* p) {
    uint32_t a;
    asm("{ .reg .u64 t; cvta.to.shared.u64 t, %1; cvt.u32.u64 %0, t; }" : "=r"(a) : "l"(p));
    return a;
}
__device__ __forceinline__ float to_tf32(float x) {
    float r; asm("cvt.rna.tf32.f32 %0, %1;" : "=f"(r) : "f"(x)); return r;
}
__device__ __forceinline__ void cp_async16(uint32_t saddr, const void* gaddr) {
    asm volatile("cp.async.cg.shared.global [%0], [%1], 16;" :: "r"(saddr), "l"(gaddr) : "memory");
}
#define CP_COMMIT() asm volatile("cp.async.commit_group;" ::: "memory")
#define CP_WAIT1()  asm volatile("cp.async.wait_group 1;" ::: "memory")

__device__ __forceinline__ void mma_tf32(float* d, const uint32_t* a, const uint32_t* b) {
    asm volatile(
        "mma.sync.aligned.m16n8k8.row.col.f32.tf32.tf32.f32 "
        "{%0,%1,%2,%3}, {%4,%5,%6,%7}, {%8,%9}, {%0,%1,%2,%3};\n"
        : "+f"(d[0]), "+f"(d[1]), "+f"(d[2]), "+f"(d[3])
        : "r"(a[0]), "r"(a[1]), "r"(a[2]), "r"(a[3]), "r"(b[0]), "r"(b[1]));
}
__device__ __forceinline__ void mma_bf16(float* d, const uint32_t* a, const uint32_t* b) {
    asm volatile(
        "mma.sync.aligned.m16n8k16.row.col.f32.bf16.bf16.f32 "
        "{%0,%1,%2,%3}, {%4,%5,%6,%7}, {%8,%9}, {%0,%1,%2,%3};\n"
        : "+f"(d[0]), "+f"(d[1]), "+f"(d[2]), "+f"(d[3])
        : "r"(a[0]), "r"(a[1]), "r"(a[2]), "r"(a[3]), "r"(b[0]), "r"(b[1]));
}
__device__ __forceinline__ void ldsm_x4(uint32_t* r, uint32_t saddr) {
    asm volatile("ldmatrix.sync.aligned.m8n8.x4.shared.b16 {%0,%1,%2,%3}, [%4];"
                 : "=r"(r[0]), "=r"(r[1]), "=r"(r[2]), "=r"(r[3]) : "r"(saddr));
}

// ---------------------------------------------------------------------------
// Precompute GEMM (tf32 mma, fp32 in/out):
//   z=0: C0 = A0 @ B0      z=1: C1 = A1 @ B1, or sub - A1@B1 if sub != 0
// ---------------------------------------------------------------------------
__global__ __launch_bounds__(256, 1) void gemm_pre_tf32(
    const float* __restrict__ A0, const float* __restrict__ A1,
    const float* __restrict__ B0, const float* __restrict__ B1,
    float* __restrict__ C0, float* __restrict__ C1,
    const float* __restrict__ sub)
{
    extern __shared__ __align__(1024) char smem[];
    const uint32_t sbase = smem_u32(smem);
    float* smf = reinterpret_cast<float*>(smem);

    const int tid  = threadIdx.x;
    const int wid  = tid >> 5;
    const int lane = tid & 31;
    const int wm   = wid >> 1;
    const int wn   = wid & 1;
    const int qrow = lane >> 2;
    const int qcol = lane & 3;

    const int row0 = blockIdx.x * PRE_BM;
    const int col0 = blockIdx.y * PRE_BN;
    const float* gA = (blockIdx.z ? A1 : A0) + (size_t)row0 * 1024;
    const float* gB = (blockIdx.z ? B1 : B0) + col0;
    float* gC = (blockIdx.z ? C1 : C0);
    const float* gSub = (blockIdx.z && sub) ? sub : nullptr;

    float acc[4][4][4];
#pragma unroll
    for (int mt = 0; mt < 4; mt++)
#pragma unroll
        for (int nt = 0; nt < 4; nt++)
#pragma unroll
            for (int q = 0; q < 4; q++) acc[mt][nt][q] = 0.0f;

    const int a_row = tid >> 3;
    const int a_chk = tid & 7;
    const int b_k   = tid >> 4;
    const int b_chk = tid & 15;

#define PRE_LOAD(it, slot)                                                           \
    do {                                                                             \
        const uint32_t sa = sbase + (slot) * PRE_STAGE_BYTES;                        \
        const uint32_t sb = sa + PRE_A_BYTES;                                        \
        const int koff = (it) * 32;                                                  \
        _Pragma("unroll")                                                            \
        for (int jj = 0; jj < 8; jj++) {                                             \
            const int r = a_row + jj * 32;                                           \
            cp_async16(sa + r * (LDAW * 4) + a_chk * 16,                             \
                       gA + (size_t)r * 1024 + koff + a_chk * 4);                    \
        }                                                                            \
        _Pragma("unroll")                                                            \
        for (int jj = 0; jj < 2; jj++) {                                             \
            const int k = b_k + jj * 16;                                             \
            cp_async16(sb + k * (PRE_LDBW * 4) + b_chk * 16,                         \
                       gB + (size_t)(koff + k) * 1024 + b_chk * 4);                  \
        }                                                                            \
    } while (0)

    PRE_LOAD(0, 0); CP_COMMIT();
    PRE_LOAD(1, 1); CP_COMMIT();

    int slot_c = 0;
    for (int it = 0; it < GEMM_ITERS; ++it) {
        CP_WAIT1();
        __syncthreads();
        if (it + 2 < GEMM_ITERS) PRE_LOAD(it + 2, (it + 2) % 3);
        CP_COMMIT();

        const float* As = smf + slot_c * (PRE_STAGE_BYTES / 4);
        const float* Bs = As + (PRE_A_BYTES / 4);
        const int arow_base = wm * 64 + qrow;
        const int bcol_base = wn * 32 + qrow;
#pragma unroll
        for (int ks = 0; ks < 4; ks++) {
            const int k0 = ks * 8;
            uint32_t af[4][4];
#pragma unroll
            for (int mt = 0; mt < 4; mt++) {
                const float* ap = As + (arow_base + mt * 16) * LDAW + k0 + qcol;
                af[mt][0] = __float_as_uint(ap[0]);
                af[mt][1] = __float_as_uint(ap[8 * LDAW]);
                af[mt][2] = __float_as_uint(ap[4]);
                af[mt][3] = __float_as_uint(ap[8 * LDAW + 4]);
            }
            uint32_t bf[4][2];
#pragma unroll
            for (int nt = 0; nt < 4; nt++) {
                const float* bp = Bs + (k0 + qcol) * PRE_LDBW + bcol_base + nt * 8;
                bf[nt][0] = __float_as_uint(bp[0]);
                bf[nt][1] = __float_as_uint(bp[4 * PRE_LDBW]);
            }
#pragma unroll
            for (int mt = 0; mt < 4; mt++)
#pragma unroll
                for (int nt = 0; nt < 4; nt++)
                    mma_tf32(acc[mt][nt], af[mt], bf[nt]);
        }
        slot_c = (slot_c + 1) % 3;
    }
#undef PRE_LOAD

#pragma unroll
    for (int mt = 0; mt < 4; mt++) {
#pragma unroll
        for (int h = 0; h < 2; h++) {
            const int n = row0 + wm * 64 + mt * 16 + h * 8 + qrow;
            const size_t base = (size_t)n * 1024 + col0 + wn * 32;
#pragma unroll
            for (int nt = 0; nt < 4; nt++) {
                float vx = acc[mt][nt][h * 2 + 0];
                float vy = acc[mt][nt][h * 2 + 1];
                const size_t off = base + nt * 8 + qcol * 2;
                if (gSub) {
                    const float2 s = *reinterpret_cast<const float2*>(gSub + off);
                    vx = s.x - vx; vy = s.y - vy;
                }
                *reinterpret_cast<float2*>(gC + off) = make_float2(vx, vy);
            }
        }
    }
}

// ---------------------------------------------------------------------------
// chanmix via tf32 mma (512 threads, 16 warps), with fused buildM:
//   blockIdx.y <  BB : channel mix (as R13)
//   blockIdx.y == BB : M2d[idx] = bf16x2(X1+Y1, X2+Y2) over 1M elems
// ---------------------------------------------------------------------------
__global__ __launch_bounds__(512, 1) void chanmix_mma(
    const float* __restrict__ x, const float* __restrict__ W,
    uint32_t* __restrict__ Uw2, float* __restrict__ U0,
    const float* __restrict__ X1, const float* __restrict__ Y1,
    const float* __restrict__ X2, const float* __restrict__ Y2,
    uint32_t* __restrict__ M2d)
{
    extern __shared__ __align__(1024) char smem[];
    const int tid = threadIdx.x;

    if (blockIdx.y == BB) {
        // fused buildM: 64 blocks x 512 thr x 32 elems = 1M
        const int base = blockIdx.x * 16384 + tid;
#pragma unroll 4
        for (int i = 0; i < 32; i++) {
            const int idx = base + i * 512;
            __nv_bfloat162 v = __floats2bfloat162_rn(X1[idx] + Y1[idx], X2[idx] + Y2[idx]);
            M2d[idx] = *reinterpret_cast<uint32_t*>(&v);
        }
        return;
    }

    float* As = reinterpret_cast<float*>(smem);
    const uint32_t sbase = smem_u32(smem);
    const uint32_t xs_base = sbase + CM_A_BYTES;

    const int wid  = tid >> 5;
    const int lane = tid & 31;
    const int qrow = lane >> 2;
    const int qcol = lane & 3;
    const int colslice = wid >> 1;   // 0..7  (32 cols each)
    const int mgroup   = wid & 1;    // 0: rows 0-47, 1: rows 48-95

    const int b = blockIdx.y;
    const int colbase0 = blockIdx.x * (CM_CHUNK * CM_NCHUNKS);

    // build A in smem: remap rows, rna-round, compensate tf32 truncation bias
    for (int idx = tid; idx < 96 * 32; idx += 512) {
        const int row = idx >> 5, c = idx & 31;
        int o, cin;
        if (row < 32) { o = row; cin = c; }
        else {
            const int seg = (row - 32) >> 4, i = (row - 32) & 15;
            o = seg * 8 + (i & 7);
            cin = ((i < 8) ? 32 : 64) + c;
        }
        As[row * CM_LDA + c] = to_tf32(W[o * 96 + cin] * 1.000344f);
    }

    const float* xb = x + (size_t)b * 32 * 65536;
    const int xrow = tid >> 4;      // 0..31 = c
    const int cpos = tid & 15;      // 16B chunk group

#define CM_LOAD(ch, slot)                                                            \
    do {                                                                             \
        const uint32_t sx = xs_base + (slot) * CM_X_BYTES;                           \
        const float* gx = xb + (size_t)xrow * 65536 + colbase0 + (ch) * CM_CHUNK;    \
        _Pragma("unroll")                                                            \
        for (int jj = 0; jj < 4; jj++)                                               \
            cp_async16(sx + xrow * (CM_LDX * 4) + (cpos + jj * 16) * 16,             \
                       gx + (cpos + jj * 16) * 4);                                   \
    } while (0)

    CM_LOAD(0, 0); CP_COMMIT();
    CM_LOAD(1, 1); CP_COMMIT();
    __syncthreads();   // As built; stage0/1 in flight

    // preload A fragments (constant across chunks)
    uint32_t af[3][4][4];
#pragma unroll
    for (int mt = 0; mt < 3; mt++) {
        const int rowb = mgroup * 48 + mt * 16 + qrow;
#pragma unroll
        for (int ks = 0; ks < 4; ks++) {
            const float* ap = As + rowb * CM_LDA + ks * 8 + qcol;
            af[mt][ks][0] = __float_as_uint(ap[0]);
            af[mt][ks][1] = __float_as_uint(ap[8 * CM_LDA]);
            af[mt][ks][2] = __float_as_uint(ap[4]);
            af[mt][ks][3] = __float_as_uint(ap[8 * CM_LDA + 4]);
        }
    }

    for (int ch = 0; ch < CM_NCHUNKS; ++ch) {
        CP_WAIT1();
        __syncthreads();
        if (ch + 2 < CM_NCHUNKS) CM_LOAD(ch + 2, (ch + 2) % 3);
        CP_COMMIT();

        const float* Xs = reinterpret_cast<const float*>(
            smem + CM_A_BYTES + (ch % 3) * CM_X_BYTES);

        float acc[3][4][4];
#pragma unroll
        for (int mt = 0; mt < 3; mt++)
#pragma unroll
            for (int nt = 0; nt < 4; nt++)
#pragma unroll
                for (int q = 0; q < 4; q++) acc[mt][nt][q] = 0.0f;

#pragma unroll
        for (int ks = 0; ks < 4; ks++) {
            uint32_t bf[4][2];
#pragma unroll
            for (int nt = 0; nt < 4; nt++) {
                const float* bp = Xs + (ks * 8 + qcol) * CM_LDX
                                  + colslice * 32 + nt * 8 + qrow;
                bf[nt][0] = __float_as_uint(bp[0]);
                bf[nt][1] = __float_as_uint(bp[4 * CM_LDX]);
            }
#pragma unroll
            for (int mt = 0; mt < 3; mt++)
#pragma unroll
                for (int nt = 0; nt < 4; nt++)
                    mma_tf32(acc[mt][nt], af[mt][ks], bf[nt]);
        }

        // epilogue: this warp's 32 cols = half of one n (t in [tb, tb+32))
        const int col0 = colbase0 + ch * CM_CHUNK + colslice * 32;
        const int n  = col0 >> 6;
        const int tb = col0 & 63;   // 0 or 32
        const size_t obase = (size_t)n * JDIM + (size_t)b * 2048 + tb;
#pragma unroll
        for (int mt = 0; mt < 3; mt++) {
            const int R = mgroup * 48 + mt * 16;
            if (R < 32) {
#pragma unroll
                for (int h = 0; h < 2; h++) {
                    const int o = R + h * 8 + qrow;
                    float* dst = U0 + obase + (size_t)o * 64;
#pragma unroll
                    for (int nt = 0; nt < 4; nt++)
                        *reinterpret_cast<float2*>(dst + nt * 8 + qcol * 2) =
                            make_float2(acc[mt][nt][h * 2 + 0], acc[mt][nt][h * 2 + 1]);
                }
            } else {
                const int seg = (R - 32) >> 4;
                const int o = seg * 8 + qrow;
                uint32_t* dst = Uw2 + obase + (size_t)o * 64;
#pragma unroll
                for (int nt = 0; nt < 4; nt++) {
                    __nv_bfloat162 p0 = __floats2bfloat162_rn(acc[mt][nt][0], acc[mt][nt][2]);
                    __nv_bfloat162 p1 = __floats2bfloat162_rn(acc[mt][nt][1], acc[mt][nt][3]);
                    uint2 v;
                    v.x = *reinterpret_cast<uint32_t*>(&p0);
                    v.y = *reinterpret_cast<uint32_t*>(&p1);
                    *reinterpret_cast<uint2*>(dst + nt * 8 + qcol * 2) = v;
                }
            }
        }
    }
#undef CM_LOAD
}

// ---------------------------------------------------------------------------
// Main GEMM (bf16 mma m16n8k16, CTA 128x128, 3-stage, 2 CTAs/SM):
//   D[1024 x 32768] = Mb[1024 x 2048 bf16] @ U  (U packed bf16x2 pair rows)
//   out[bz][n][t] = D[n][j] + U0[n][j] + bias[bz & 31]
// 8 warps = 4M (32 rows) x 2N (64 cols); warp tile 32x64, acc[2][8][4].
// ---------------------------------------------------------------------------
__global__ __launch_bounds__(256, 2) void main_gemm_bf16(
    const uint32_t* __restrict__ Mb2, const uint32_t* __restrict__ Uw2,
    const float* __restrict__ U0,     const float* __restrict__ bias,
    float* __restrict__ out)
{
    extern __shared__ __align__(1024) char smem[];
    const uint32_t sbase = smem_u32(smem);
    const uint32_t* smu = reinterpret_cast<uint32_t*>(smem);

    const int tid  = threadIdx.x;
    const int wid  = tid >> 5;
    const int lane = tid & 31;
    const int wm   = wid >> 1;              // 0..3, 32 rows each
    const int wn   = wid & 1;               // 0..1, 64 cols each
    const int qrow = lane >> 2;
    const int qcol = lane & 3;
    const int lrow = lane & 15;
    const int lkw  = (lane >> 4) << 2;

    const int row0 = blockIdx.x * BM;
    const int col0 = blockIdx.y * BN;

    float acc[2][8][4];
#pragma unroll
    for (int mt = 0; mt < 2; mt++)
#pragma unroll
        for (int nt = 0; nt < 8; nt++)
#pragma unroll
            for (int q = 0; q < 4; q++) acc[mt][nt][q] = 0.0f;

    const int a_row = tid >> 3;   // 0..31
    const int a_chk = tid & 7;
    const int b_k   = tid >> 5;
    const int b_chk = tid & 31;

    const char* gA = (const char*)Mb2 + (size_t)row0 * (NN * 4);
    const uint32_t* gB = Uw2 + col0;

#define MAIN_LOAD(it, slot)                                                          \
    do {                                                                             \
        const uint32_t sa = sbase + (slot) * STAGE_BYTES;                            \
        const uint32_t sb = sa + A_STAGE_BYTES;                                      \
        _Pragma("unroll")                                                            \
        for (int jj = 0; jj < 4; jj++) {                                             \
            const int r = a_row + jj * 32;                                           \
            cp_async16(sa + r * (LDAW * 4) + a_chk * 16,                             \
                       gA + (size_t)r * (NN * 4) + (it) * 128 + a_chk * 16);         \
        }                                                                            \
        _Pragma("unroll")                                                            \
        for (int jj = 0; jj < 4; jj++) {                                             \
            const int k = b_k + jj * 8;                                              \
            cp_async16(sb + k * (LDBW * 4) + b_chk * 16,                             \
                       gB + (size_t)((it) * 32 + k) * JDIM + b_chk * 4);             \
        }                                                                            \
    } while (0)

    MAIN_LOAD(0, 0); CP_COMMIT();
    MAIN_LOAD(1, 1); CP_COMMIT();

    int slot_c = 0;
    for (int it = 0; it < GEMM_ITERS; ++it) {
        CP_WAIT1();
        __syncthreads();
        if (it + 2 < GEMM_ITERS) MAIN_LOAD(it + 2, (it + 2) % 3);
        CP_COMMIT();

        const uint32_t As_b = sbase + slot_c * STAGE_BYTES;
        const uint32_t* Bs = smu + slot_c * (STAGE_BYTES / 4) + (A_STAGE_BYTES / 4);
        const int bcol_base = wn * 64 + qrow;
#pragma unroll
        for (int ks = 0; ks < 4; ks++) {
            const int kw = ks * 8 + qcol;
            uint32_t af[2][4];
#pragma unroll
            for (int mt = 0; mt < 2; mt++) {
                const uint32_t addr = As_b +
                    (uint32_t)(((wm * 32 + mt * 16 + lrow) * LDAW) + ks * 8 + lkw) * 4;
                ldsm_x4(af[mt], addr);
            }
            uint32_t bf[8][2];
#pragma unroll
            for (int nt = 0; nt < 8; nt++) {
                const uint32_t* bp = Bs + kw * LDBW + bcol_base + nt * 8;
                bf[nt][0] = bp[0];
                bf[nt][1] = bp[4 * LDBW];
            }
#pragma unroll
            for (int mt = 0; mt < 2; mt++)
#pragma unroll
                for (int nt = 0; nt < 8; nt++)
                    mma_bf16(acc[mt][nt], af[mt], bf[nt]);
        }
        slot_c = (slot_c + 1) % 3;
    }
#undef MAIN_LOAD

    // ---- epilogue: + U0 + bias, scatter to out[bz][n][t] ----
    const int j0 = col0 + wn * 64;
    const int bz = j0 >> 6;
    const float bv = bias[bz & 31];
#pragma unroll
    for (int mt = 0; mt < 2; mt++) {
#pragma unroll
        for (int h = 0; h < 2; h++) {
            const int n = row0 + wm * 32 + mt * 16 + h * 8 + qrow;
            float* orow = out + (size_t)bz * (NN * TT) + (size_t)n * TT;
            const float* u0row = U0 + (size_t)n * JDIM + j0;
#pragma unroll
            for (int nt = 0; nt < 8; nt++) {
                const int t = nt * 8 + qcol * 2;
                const float2 u = *reinterpret_cast<const float2*>(u0row + t);
                float2 v;
                v.x = acc[mt][nt][h * 2 + 0] + u.x + bv;
                v.y = acc[mt][nt][h * 2 + 1] + u.y + bv;
                *reinterpret_cast<float2*>(orow + t) = v;
            }
        }
    }
}

// ---------------------------------------------------------------------------
// Launch  (4 launches; profiler lands on #4 = main_gemm_bf16)
// ---------------------------------------------------------------------------
extern "C" void kernel_launch(void* const* d_in, const int* in_sizes, int n_in,
                              void* d_out, int out_size)
{
    const float* x  = (const float*)d_in[0];
    const float* AL = (const float*)d_in[1];
    const float* AS = (const float*)d_in[2];
    const float* W  = (const float*)d_in[3];
    const float* bm = (const float*)d_in[4];
    float* out = (float*)d_out;

    uint32_t *pUw2, *pM2;
    float *pU0, *pG1, *pS, *pG2p, *pG1p;
    cudaGetSymbolAddress((void**)&pUw2, g_Uw2);
    cudaGetSymbolAddress((void**)&pU0,  g_U0);
    cudaGetSymbolAddress((void**)&pM2,  g_M2);
    cudaGetSymbolAddress((void**)&pG1,  g_G1);
    cudaGetSymbolAddress((void**)&pS,   g_S);
    cudaGetSymbolAddress((void**)&pG2p, g_G2p);
    cudaGetSymbolAddress((void**)&pG1p, g_G1p);

    cudaFuncSetAttribute(gemm_pre_tf32,
                         cudaFuncAttributeMaxDynamicSharedMemorySize, SMEM_PRE);
    cudaFuncSetAttribute(chanmix_mma,
                         cudaFuncAttributeMaxDynamicSharedMemorySize, SMEM_CM);
    cudaFuncSetAttribute(main_gemm_bf16,
                         cudaFuncAttributeMaxDynamicSharedMemorySize, SMEM_MAIN);

    const dim3 gpre(1024 / PRE_BM, 1024 / PRE_BN, 2);   // 4 x 16 x 2 = 128 CTAs

    // 1) stage 1: G1 = AL^2 ; S = AS - AS*AL (subtract fused into z=1 epilogue)
    gemm_pre_tf32<<<gpre, 256, SMEM_PRE>>>(AL, AS, AL, AL, pG1, pS, AS);

    // 2) stage 2: G2p = AL*G1 (=AL^3) ; G1p = AS*S (=AS^2(I-AL))
    gemm_pre_tf32<<<gpre, 256, SMEM_PRE>>>(AL, AS, pG1, pS, pG2p, pG1p, nullptr);

    // 3) channel mix on tensor cores + fused buildM (blockIdx.y == BB)
    chanmix_mma<<<dim3(65536 / (CM_CHUNK * CM_NCHUNKS), BB + 1), 512, SMEM_CM>>>(
        x, W, pUw2, pU0, pG1, pS, pG2p, pG1p, pM2);

    // 4) main bf16 tensor GEMM + fused epilogue (2 CTAs/SM; row tiles fast)
    main_gemm_bf16<<<dim3(NN / BM, JDIM / BN), 256, SMEM_MAIN>>>(pM2, pUw2, pU0, bm, out);
}